// round 2
// baseline (speedup 1.0000x reference)
#include <cuda_runtime.h>
#include <cstdint>

// Problem constants
#define B_   128
#define N_   1024
#define DMX  64
#define DIN  68
#define READ_ELEMS (B_ * N_)          // 131072

// Scratch (device globals; no allocations allowed)
__device__ float g_C[2 * DMX * DIN];                 // combined W_gc_s @ W_in : [s*64+o][d]
__device__ float g_cb[2 * DMX];                      // combined bias (W_gc_s @ b_in)
__device__ float g_Y[2u * B_ * DMX * N_];            // [s][b][o][v]  64 MB
__device__ float g_G[(size_t)B_ * DMX * N_];         // [b][o][w]     32 MB

// ---------------- f32x2 packed-FMA helpers (sm_10x) ----------------
__device__ __forceinline__ unsigned long long pk2(float v) {
    unsigned long long r;
    asm("mov.b64 %0, {%1, %1};" : "=l"(r) : "f"(v));
    return r;
}
__device__ __forceinline__ void ffma2(unsigned long long& d,
                                      unsigned long long a,
                                      unsigned long long b) {
    asm("fma.rn.f32x2 %0, %1, %2, %0;" : "+l"(d) : "l"(a), "l"(b));
}
__device__ __forceinline__ float2 upk2(unsigned long long v) {
    float2 r;
    asm("mov.b64 {%0, %1}, %2;" : "=f"(r.x), "=f"(r.y) : "l"(v));
    return r;
}

// ---------------- K0: fold W_gc into W_in ----------------
// g_C[(s*64+o)][d] = sum_c W_gc[o, s*64+c] * W_in[c, d]
// g_cb[s*64+o]     = sum_c W_gc[o, s*64+c] * b_in[c]
__global__ void k0_combine(const float* __restrict__ W_gc,
                           const float* __restrict__ W_in,
                           const float* __restrict__ b_in) {
    int d = blockIdx.x;          // 0..67
    int t = threadIdx.x;         // 0..127 -> (s,o)
    int s = t >> 6, o = t & 63;
    const float* wg = W_gc + o * 128 + s * 64;
    float acc = 0.f;
#pragma unroll 8
    for (int c = 0; c < 64; ++c) acc += wg[c] * W_in[c * DIN + d];
    g_C[t * DIN + d] = acc;
    if (d == 0) {
        float ab = 0.f;
        for (int c = 0; c < 64; ++c) ab += wg[c] * b_in[c];
        g_cb[t] = ab;
    }
}

// ---------------- K1: Y[s][b][o][v] = C @ cat(x,m,u,h) + cb ----------------
// Per batch: [128 rows x 68] @ [68 x 1024].  Grid (N/64, B), 256 thr.
__global__ void k1_yin(const float* __restrict__ x, const float* __restrict__ m,
                       const float* __restrict__ u, const float* __restrict__ h) {
    __shared__ float sA[34][128];   // [d-chunk][row]
    __shared__ float sB[34][64];    // [d-chunk][v]
    const int b = blockIdx.y;
    const int v0 = blockIdx.x * 64;
    const int t  = threadIdx.x;
    const int ty = t >> 4, tx = t & 15;
    const int m0 = ty * 8, n0 = tx * 4;

    float acc[8][4];
#pragma unroll
    for (int i = 0; i < 8; ++i)
#pragma unroll
        for (int j = 0; j < 4; ++j) acc[i][j] = 0.f;

    for (int kc = 0; kc < 2; ++kc) {
        const int d0 = kc * 34;
        // A chunk: g_C transposed to [d][row]
        for (int e = t; e < 34 * 128; e += 256) {
            int dd = e >> 7, so = e & 127;
            sA[dd][so] = g_C[so * DIN + d0 + dd];
        }
        // B chunk: gather of concat(x,m,u,h) rows
        for (int e = t; e < 34 * 64; e += 256) {
            int dd = e >> 6, vv = e & 63;
            int d = d0 + dd, v = v0 + vv;
            float val;
            if (d == 0)      val = x[b * N_ + v];
            else if (d == 1) val = m[b * N_ + v];
            else if (d < 4)  val = u[(b * 2 + (d - 2)) * N_ + v];
            else             val = h[((size_t)b * 64 + (d - 4)) * N_ + v];
            sB[dd][vv] = val;
        }
        __syncthreads();
#pragma unroll
        for (int dd = 0; dd < 34; ++dd) {
            float4 a0 = *(const float4*)&sA[dd][m0];
            float4 a1 = *(const float4*)&sA[dd][m0 + 4];
            float4 bv = *(const float4*)&sB[dd][n0];
            float am[8] = {a0.x, a0.y, a0.z, a0.w, a1.x, a1.y, a1.z, a1.w};
            float bb[4] = {bv.x, bv.y, bv.z, bv.w};
#pragma unroll
            for (int i = 0; i < 8; ++i)
#pragma unroll
                for (int j = 0; j < 4; ++j) acc[i][j] += am[i] * bb[j];
        }
        __syncthreads();
    }
#pragma unroll
    for (int i = 0; i < 8; ++i) {
        int so = m0 + i;
        int s = so >> 6, o = so & 63;
        float bias = g_cb[so];
        float4 r;
        r.x = acc[i][0] + bias; r.y = acc[i][1] + bias;
        r.z = acc[i][2] + bias; r.w = acc[i][3] + bias;
        *(float4*)&g_Y[(((size_t)s * B_ + b) * 64 + o) * N_ + v0 + n0] = r;
    }
}

// ---------------- K2: the big NT GEMM ----------------
// G[r][w] = b_gc[r&63] + sum_s sum_v Y_s[r][v] * adj[s][w][v]
// M=8192, Nc=1024, K=2x1024.  128x128 block tile, BK=32, 8x8 thread tile, FFMA2.
__global__ void __launch_bounds__(256, 2)
k2_gemm(const float* __restrict__ adj, const float* __restrict__ b_gc) {
    __shared__ float sA[32][136];   // [k][row], +8 pad: conflict-free transposed stores
    __shared__ float sB[32][136];   // [k][w]
    const int t  = threadIdx.x;
    const int ty = t >> 4, tx = t & 15;
    const int m0 = ty * 8, n0 = tx * 8;
    const int r0 = blockIdx.y * 128;          // row tile (b*64+o)
    const int w0 = blockIdx.x * 128;          // w tile

    unsigned long long acc2[8][4];
#pragma unroll
    for (int i = 0; i < 8; ++i)
#pragma unroll
        for (int j = 0; j < 4; ++j) acc2[i][j] = 0ull;

    for (int s = 0; s < 2; ++s) {
        const float* Ab = g_Y + (size_t)s * (B_ * DMX * N_) + (size_t)r0 * N_;
        const float* Bb = adj + (size_t)s * (N_ * N_) + (size_t)w0 * N_;
        for (int v0 = 0; v0 < N_; v0 += 32) {
#pragma unroll
            for (int q = 0; q < 4; ++q) {
                int f  = t + q * 256;           // float4 index 0..1023
                int r  = f >> 3;
                int vv = (f & 7) * 4;
                float4 av = *(const float4*)&Ab[(size_t)r * N_ + v0 + vv];
                sA[vv + 0][r] = av.x; sA[vv + 1][r] = av.y;
                sA[vv + 2][r] = av.z; sA[vv + 3][r] = av.w;
                float4 bv = *(const float4*)&Bb[(size_t)r * N_ + v0 + vv];
                sB[vv + 0][r] = bv.x; sB[vv + 1][r] = bv.y;
                sB[vv + 2][r] = bv.z; sB[vv + 3][r] = bv.w;
            }
            __syncthreads();
#pragma unroll
            for (int k = 0; k < 32; ++k) {
                float4 a0 = *(const float4*)&sA[k][m0];
                float4 a1 = *(const float4*)&sA[k][m0 + 4];
                ulonglong2 bq0 = *(const ulonglong2*)&sB[k][n0];
                ulonglong2 bq1 = *(const ulonglong2*)&sB[k][n0 + 4];
                unsigned long long av[8] = {pk2(a0.x), pk2(a0.y), pk2(a0.z), pk2(a0.w),
                                            pk2(a1.x), pk2(a1.y), pk2(a1.z), pk2(a1.w)};
                unsigned long long bv[4] = {bq0.x, bq0.y, bq1.x, bq1.y};
#pragma unroll
                for (int i = 0; i < 8; ++i)
#pragma unroll
                    for (int j = 0; j < 4; ++j) ffma2(acc2[i][j], av[i], bv[j]);
            }
            __syncthreads();
        }
    }
#pragma unroll
    for (int i = 0; i < 8; ++i) {
        int R = r0 + m0 + i;
        float bias = b_gc[R & 63];
        float buf[8];
#pragma unroll
        for (int j = 0; j < 4; ++j) {
            float2 p = upk2(acc2[i][j]);
            buf[2 * j]     = p.x + bias;
            buf[2 * j + 1] = p.y + bias;
        }
        *(float4*)&g_G[(size_t)R * N_ + w0 + n0]     = *(float4*)&buf[0];
        *(float4*)&g_G[(size_t)R * N_ + w0 + n0 + 4] = *(float4*)&buf[4];
    }
}

// ---------------- K3: out-conv + PReLU + h-copy ----------------
// pre[o][n] = b_out[o] + sum_c Wout[o,c]*gc[c][n] + Wout[o,64+c]*h[c][n]
// out[b][0:64]  = prelu(pre), out[b][64:128] = h
__global__ void k3_out(const float* __restrict__ h, const float* __restrict__ W_out,
                       const float* __restrict__ b_out, const float* __restrict__ prelu_w,
                       float* __restrict__ out) {
    __shared__ float sW[32][64];
    __shared__ float sD[32][64];
    const int b  = blockIdx.y;
    const int v0 = blockIdx.x * 64;
    const int t  = threadIdx.x;
    const int ty = t >> 4, tx = t & 15;
    const int o0 = ty * 4, n0 = tx * 4;

    float acc[4][4];
#pragma unroll
    for (int i = 0; i < 4; ++i)
#pragma unroll
        for (int j = 0; j < 4; ++j) acc[i][j] = 0.f;

    for (int kc = 0; kc < 4; ++kc) {
        const int k0 = kc * 32;
        for (int e = t; e < 32 * 64; e += 256) {
            int kk = e >> 6, o = e & 63;
            sW[kk][o] = W_out[o * 128 + k0 + kk];
        }
        for (int e = t; e < 32 * 64; e += 256) {
            int kk = e >> 6, vv = e & 63;
            int k = k0 + kk;
            sD[kk][vv] = (k < 64)
                ? g_G[((size_t)b * 64 + k) * N_ + v0 + vv]
                : h[((size_t)b * 64 + (k - 64)) * N_ + v0 + vv];
        }
        __syncthreads();
#pragma unroll
        for (int kk = 0; kk < 32; ++kk) {
            float4 a = *(const float4*)&sW[kk][o0];
            float4 d = *(const float4*)&sD[kk][n0];
            float am[4] = {a.x, a.y, a.z, a.w};
            float dm[4] = {d.x, d.y, d.z, d.w};
#pragma unroll
            for (int i = 0; i < 4; ++i)
#pragma unroll
                for (int j = 0; j < 4; ++j) acc[i][j] += am[i] * dm[j];
        }
        __syncthreads();
    }
    const float pw = prelu_w[0];
#pragma unroll
    for (int i = 0; i < 4; ++i) {
        int o = o0 + i;
        float bo = b_out[o];
        float buf[4];
#pragma unroll
        for (int j = 0; j < 4; ++j) {
            float v = acc[i][j] + bo;
            buf[j] = (v >= 0.f) ? v : pw * v;
        }
        *(float4*)&out[((size_t)b * 128 + o) * N_ + v0 + n0] = *(float4*)&buf[0];
    }
    // copy h into out[b][64:128]
    for (int e4 = t; e4 < 16 * 64; e4 += 256) {
        int c = e4 >> 4, vv = (e4 & 15) * 4;
        *(float4*)&out[((size_t)b * 128 + 64 + c) * N_ + v0 + vv] =
            *(const float4*)&h[((size_t)b * 64 + c) * N_ + v0 + vv];
    }
}

// ---------------- K4: readout  read[b][n] = b_read + W_read . out[b][:][n] ----------------
__global__ void k4_read(const float* __restrict__ W_read, const float* __restrict__ b_read,
                        const float* __restrict__ out, float* __restrict__ rd) {
    __shared__ float sw[128];
    const int b = blockIdx.y;
    const int n = blockIdx.x * 256 + threadIdx.x;
    if (threadIdx.x < 128) sw[threadIdx.x] = W_read[threadIdx.x];
    __syncthreads();
    float acc = b_read[0];
    const float* p = out + (size_t)b * 128 * N_ + n;
#pragma unroll 8
    for (int c = 0; c < 128; ++c) acc += sw[c] * p[(size_t)c * N_];
    rd[b * N_ + n] = acc;
}

extern "C" void kernel_launch(void* const* d_in, const int* in_sizes, int n_in,
                              void* d_out, int out_size) {
    const float* x       = (const float*)d_in[0];
    const float* m       = (const float*)d_in[1];
    const float* u       = (const float*)d_in[2];
    const float* h       = (const float*)d_in[3];
    const float* adj     = (const float*)d_in[4];
    const float* W_in    = (const float*)d_in[5];
    const float* b_in    = (const float*)d_in[6];
    const float* W_gc    = (const float*)d_in[7];
    const float* b_gc    = (const float*)d_in[8];
    const float* W_out   = (const float*)d_in[9];
    const float* b_out   = (const float*)d_in[10];
    const float* W_read  = (const float*)d_in[11];
    const float* b_read  = (const float*)d_in[12];
    const float* prelu_w = (const float*)d_in[13];

    float* read_out = (float*)d_out;                   // [B,1,N]   first tuple element
    float* out_big  = (float*)d_out + READ_ELEMS;      // [B,128,N] second tuple element

    k0_combine<<<68, 128>>>(W_gc, W_in, b_in);
    k1_yin<<<dim3(N_ / 64, B_), 256>>>(x, m, u, h);
    k2_gemm<<<dim3(N_ / 128, (B_ * DMX) / 128), 256>>>(adj, b_gc);
    k3_out<<<dim3(N_ / 64, B_), 256>>>(h, W_out, b_out, prelu_w, out_big);
    k4_read<<<dim3(N_ / 256, B_), 256>>>(W_read, b_read, out_big, read_out);
}

// round 4
// speedup vs baseline: 1.9160x; 1.9160x over previous
#include <cuda_runtime.h>
#include <cstdint>

// Problem constants
#define B_   128
#define N_   1024
#define DMX  64
#define DIN  68
#define READ_ELEMS (B_ * N_)

// Scratch (device globals; no allocations allowed)
__device__ float g_C[2 * DMX * DIN];         // combined W_gc_s @ W_in : [s*64+o][d]
__device__ float g_cb[2 * DMX];              // combined bias
__device__ float g_Y[2u * B_ * DMX * N_];    // [s][r=b*64+o][v]  64 MB
__device__ float g_G[(size_t)B_ * DMX * N_]; // [r=b*64+o][w]     32 MB

// ================= f32x2 packed-FMA helpers =================
__device__ __forceinline__ unsigned long long pk2(float v) {
    unsigned long long r;
    asm("mov.b64 %0, {%1, %1};" : "=l"(r) : "f"(v));
    return r;
}
__device__ __forceinline__ void ffma2(unsigned long long& d,
                                      unsigned long long a,
                                      unsigned long long b) {
    asm("fma.rn.f32x2 %0, %1, %2, %0;" : "+l"(d) : "l"(a), "l"(b));
}
__device__ __forceinline__ float2 upk2(unsigned long long v) {
    float2 r;
    asm("mov.b64 {%0, %1}, %2;" : "=f"(r.x), "=f"(r.y) : "l"(v));
    return r;
}

// ================= warp-level tf32 MMA helpers (base ISA, sm_80+) =================
__device__ __forceinline__ uint32_t f2tf32(float x) {
    uint32_t u;
    asm("cvt.rna.tf32.f32 %0, %1;" : "=r"(u) : "f"(x));
    return u;
}
__device__ __forceinline__ void mma16n8k8(float* c, const uint32_t* a, const uint32_t* b) {
    asm volatile(
        "mma.sync.aligned.m16n8k8.row.col.f32.tf32.tf32.f32 "
        "{%0,%1,%2,%3}, {%4,%5,%6,%7}, {%8,%9}, {%0,%1,%2,%3};"
        : "+f"(c[0]), "+f"(c[1]), "+f"(c[2]), "+f"(c[3])
        : "r"(a[0]), "r"(a[1]), "r"(a[2]), "r"(a[3]),
          "r"(b[0]), "r"(b[1]));
}

// ================= K0: fold W_gc into W_in =================
__global__ void k0_combine(const float* __restrict__ W_gc,
                           const float* __restrict__ W_in,
                           const float* __restrict__ b_in) {
    int d = blockIdx.x;          // 0..67
    int t = threadIdx.x;         // 0..127 -> (s,o)
    int s = t >> 6, o = t & 63;
    const float* wg = W_gc + o * 128 + s * 64;
    float acc = 0.f;
#pragma unroll 8
    for (int c = 0; c < 64; ++c) acc += wg[c] * W_in[c * DIN + d];
    g_C[t * DIN + d] = acc;
    if (d == 0) {
        float ab = 0.f;
        for (int c = 0; c < 64; ++c) ab += wg[c] * b_in[c];
        g_cb[t] = ab;
    }
}

// ================= K1: Y = C @ cat(x,m,u,h) + cb =================
__global__ void __launch_bounds__(256) k1_yin(const float* __restrict__ x,
                                              const float* __restrict__ m,
                                              const float* __restrict__ u,
                                              const float* __restrict__ h) {
    __shared__ float sA[34][136];   // [d][row]
    __shared__ float sB[34][136];   // [d][v]
    const int b  = blockIdx.y;
    const int v0 = blockIdx.x * 128;
    const int t  = threadIdx.x;
    const int ty = t >> 4, tx = t & 15;
    const int m0 = ty * 8, n0 = tx * 8;

    unsigned long long acc2[8][4];
#pragma unroll
    for (int i = 0; i < 8; ++i)
#pragma unroll
        for (int j = 0; j < 4; ++j) acc2[i][j] = 0ull;

    for (int kc = 0; kc < 2; ++kc) {
        const int d0 = kc * 34;
        for (int e = t; e < 34 * 128; e += 256) {
            int dd = e >> 7, so = e & 127;
            sA[dd][so] = g_C[so * DIN + d0 + dd];
        }
        for (int e = t; e < 34 * 128; e += 256) {
            int dd = e >> 7, vv = e & 127;
            int d = d0 + dd, v = v0 + vv;
            float val;
            if (d == 0)      val = x[b * N_ + v];
            else if (d == 1) val = m[b * N_ + v];
            else if (d < 4)  val = u[(b * 2 + (d - 2)) * N_ + v];
            else             val = h[((size_t)b * 64 + (d - 4)) * N_ + v];
            sB[dd][vv] = val;
        }
        __syncthreads();
#pragma unroll
        for (int dd = 0; dd < 34; ++dd) {
            float4 a0 = *(const float4*)&sA[dd][m0];
            float4 a1 = *(const float4*)&sA[dd][m0 + 4];
            ulonglong2 bq0 = *(const ulonglong2*)&sB[dd][n0];
            ulonglong2 bq1 = *(const ulonglong2*)&sB[dd][n0 + 4];
            unsigned long long av[8] = {pk2(a0.x), pk2(a0.y), pk2(a0.z), pk2(a0.w),
                                        pk2(a1.x), pk2(a1.y), pk2(a1.z), pk2(a1.w)};
            unsigned long long bv[4] = {bq0.x, bq0.y, bq1.x, bq1.y};
#pragma unroll
            for (int i = 0; i < 8; ++i)
#pragma unroll
                for (int j = 0; j < 4; ++j) ffma2(acc2[i][j], av[i], bv[j]);
        }
        __syncthreads();
    }
#pragma unroll
    for (int i = 0; i < 8; ++i) {
        int so = m0 + i;
        int s = so >> 6, o = so & 63;
        float bias = g_cb[so];
        float buf[8];
#pragma unroll
        for (int j = 0; j < 4; ++j) {
            float2 p = upk2(acc2[i][j]);
            buf[2 * j]     = p.x + bias;
            buf[2 * j + 1] = p.y + bias;
        }
        float* dst = &g_Y[(((size_t)s * B_ + b) * 64 + o) * N_ + v0 + n0];
        *(float4*)dst       = *(float4*)&buf[0];
        *(float4*)(dst + 4) = *(float4*)&buf[4];
    }
}

// ================= K2: warp-MMA tf32 NT GEMM =================
// G[r][w] = b_gc[r&63] + sum_s sum_v Y_s[r][v] * adj_s[w][v]
// M=8192 (grid.y*128), N=1024 (grid.x*128), K=2*1024. BK=32.
// 8 warps: warp (wm 0..1, wn 0..3) owns a 64x32 output tile.
// Fragment-major smem staging: one v4/v2 LDS per fragment, conflict-free.
__global__ void __launch_bounds__(256, 2) k2_mma(const float* __restrict__ adj,
                                                 const float* __restrict__ b_gc) {
    // A: [ks 0..3][mf 0..7][lane 0..31][reg 0..3]  (4096 u32 = 16 KB)
    // B: [ks 0..3][nf 0..15][lane 0..31][reg 0..1] (4096 u32 = 16 KB)
    __shared__ uint32_t sA[4 * 8 * 32 * 4];
    __shared__ uint32_t sB[4 * 16 * 32 * 2];
    const int t    = threadIdx.x;
    const int lane = t & 31, wid = t >> 5;
    const int wm = wid >> 2, wn = wid & 3;
    const int r0 = blockIdx.y * 128;
    const int w0 = blockIdx.x * 128;

    float acc[4][4][4];
#pragma unroll
    for (int i = 0; i < 4; ++i)
#pragma unroll
        for (int j = 0; j < 4; ++j)
#pragma unroll
            for (int c = 0; c < 4; ++c) acc[i][j][c] = 0.f;

    for (int kc = 0; kc < 64; ++kc) {
        const int s  = kc >> 5;
        const int vc = (kc & 31) * 32;
        const float* Ab = g_Y + (size_t)s * (B_ * DMX * N_) + (size_t)r0 * N_ + vc;
        const float* Bb = adj + (size_t)s * (N_ * N_) + (size_t)w0 * N_ + vc;
        __syncthreads();
#pragma unroll
        for (int q = 0; q < 4; ++q) {
            const int f  = t + q * 256;      // 0..1023
            const int r  = f >> 3;           // 0..127
            const int c4 = (f & 7) * 4;      // 0..28
            const int ks = c4 >> 3;
            const int th = (c4 >> 2) & 1;
            // ---- A ----
            {
                float4 av = *(const float4*)(Ab + (size_t)r * N_ + c4);
                const int mf = r >> 4, row_in = r & 15;
                const int g = row_in & 7, hi = row_in >> 3;
                uint32_t* base = &sA[(((ks * 8 + mf) * 32) + g * 4) * 4 + hi + 2 * th];
                base[0]  = f2tf32(av.x);
                base[4]  = f2tf32(av.y);
                base[8]  = f2tf32(av.z);
                base[12] = f2tf32(av.w);
            }
            // ---- B ----
            {
                float4 bv = *(const float4*)(Bb + (size_t)r * N_ + c4);
                const int nf = r >> 3, n_in = r & 7;
                uint32_t* base = &sB[(((ks * 16 + nf) * 32) + n_in * 4) * 2 + th];
                base[0] = f2tf32(bv.x);
                base[2] = f2tf32(bv.y);
                base[4] = f2tf32(bv.z);
                base[6] = f2tf32(bv.w);
            }
        }
        __syncthreads();
#pragma unroll
        for (int ks = 0; ks < 4; ++ks) {
            uint32_t af[4][4];
#pragma unroll
            for (int i = 0; i < 4; ++i) {
                uint4 v = *(const uint4*)&sA[((ks * 8 + wm * 4 + i) * 32 + lane) * 4];
                af[i][0] = v.x; af[i][1] = v.y; af[i][2] = v.z; af[i][3] = v.w;
            }
            uint32_t bf[4][2];
#pragma unroll
            for (int j = 0; j < 4; ++j) {
                uint2 v = *(const uint2*)&sB[((ks * 16 + wn * 4 + j) * 32 + lane) * 2];
                bf[j][0] = v.x; bf[j][1] = v.y;
            }
#pragma unroll
            for (int i = 0; i < 4; ++i)
#pragma unroll
                for (int j = 0; j < 4; ++j)
                    mma16n8k8(acc[i][j], af[i], bf[j]);
        }
    }

    // epilogue: add bias, store
    const int g = lane >> 2, tq = lane & 3;
#pragma unroll
    for (int i = 0; i < 4; ++i) {
        const int rloc = wm * 64 + i * 16 + g;
        const float bias0 = b_gc[(rloc) & 63];
        const float bias1 = b_gc[(rloc + 8) & 63];
        float* row0 = &g_G[(size_t)(r0 + rloc) * N_ + w0 + wn * 32 + 2 * tq];
        float* row1 = row0 + 8 * N_;
#pragma unroll
        for (int j = 0; j < 4; ++j) {
            float2 v0 = {acc[i][j][0] + bias0, acc[i][j][1] + bias0};
            float2 v1 = {acc[i][j][2] + bias1, acc[i][j][3] + bias1};
            *(float2*)(row0 + j * 8) = v0;
            *(float2*)(row1 + j * 8) = v1;
        }
    }
}

// ================= K34: out-conv + PReLU + h-copy + fused readout =================
__global__ void __launch_bounds__(128) k34_out(const float* __restrict__ h,
                                               const float* __restrict__ W_out,
                                               const float* __restrict__ b_out,
                                               const float* __restrict__ prelu_w,
                                               const float* __restrict__ W_read,
                                               const float* __restrict__ b_read,
                                               float* __restrict__ out,
                                               float* __restrict__ rd) {
    __shared__ float sW[32][68];     // [k][o]
    __shared__ float sD[32][136];    // [k][n]
    __shared__ float sWr[128];
    __shared__ float sred[8][128];
    const int b  = blockIdx.y;
    const int v0 = blockIdx.x * 128;
    const int t  = threadIdx.x;
    const int ty = t >> 4, tx = t & 15;
    const int o0 = ty * 8, n0 = tx * 8;

    if (t < 128) sWr[t] = W_read[t];

    unsigned long long acc2[8][4];
#pragma unroll
    for (int i = 0; i < 8; ++i)
#pragma unroll
        for (int j = 0; j < 4; ++j) acc2[i][j] = 0ull;

    for (int kc = 0; kc < 4; ++kc) {
        const int k0 = kc * 32;
        for (int e = t; e < 32 * 64; e += 128) {
            int kk = e >> 6, o = e & 63;
            sW[kk][o] = W_out[o * 128 + k0 + kk];
        }
        for (int e = t; e < 32 * 128; e += 128) {
            int kk = e >> 7, vv = e & 127;
            int k = k0 + kk;
            sD[kk][vv] = (k < 64)
                ? g_G[((size_t)b * 64 + k) * N_ + v0 + vv]
                : h[((size_t)b * 64 + (k - 64)) * N_ + v0 + vv];
        }
        __syncthreads();
#pragma unroll
        for (int kk = 0; kk < 32; ++kk) {
            float4 a0 = *(const float4*)&sW[kk][o0];
            float4 a1 = *(const float4*)&sW[kk][o0 + 4];
            ulonglong2 bq0 = *(const ulonglong2*)&sD[kk][n0];
            ulonglong2 bq1 = *(const ulonglong2*)&sD[kk][n0 + 4];
            unsigned long long av[8] = {pk2(a0.x), pk2(a0.y), pk2(a0.z), pk2(a0.w),
                                        pk2(a1.x), pk2(a1.y), pk2(a1.z), pk2(a1.w)};
            unsigned long long bv[4] = {bq0.x, bq0.y, bq1.x, bq1.y};
#pragma unroll
            for (int i = 0; i < 8; ++i)
#pragma unroll
                for (int j = 0; j < 4; ++j) ffma2(acc2[i][j], av[i], bv[j]);
        }
        __syncthreads();
    }

    const float pw = prelu_w[0];
    float rsum[8];
#pragma unroll
    for (int j = 0; j < 8; ++j) rsum[j] = 0.f;

#pragma unroll
    for (int i = 0; i < 8; ++i) {
        int o = o0 + i;
        float bo = b_out[o];
        float wro = sWr[o];
        float buf[8];
#pragma unroll
        for (int j = 0; j < 4; ++j) {
            float2 p = upk2(acc2[i][j]);
            float v0f = p.x + bo; v0f = (v0f >= 0.f) ? v0f : pw * v0f;
            float v1f = p.y + bo; v1f = (v1f >= 0.f) ? v1f : pw * v1f;
            buf[2 * j] = v0f; buf[2 * j + 1] = v1f;
            rsum[2 * j]     += wro * v0f;
            rsum[2 * j + 1] += wro * v1f;
        }
        float* dst = &out[((size_t)b * 128 + o) * N_ + v0 + n0];
        *(float4*)dst       = *(float4*)&buf[0];
        *(float4*)(dst + 4) = *(float4*)&buf[4];
    }
#pragma unroll
    for (int i = 0; i < 8; ++i) {
        int c = ty * 8 + i;
        const float* src = &h[((size_t)b * 64 + c) * N_ + v0 + n0];
        float4 h0 = *(const float4*)src;
        float4 h1 = *(const float4*)(src + 4);
        float* dst = &out[((size_t)b * 128 + 64 + c) * N_ + v0 + n0];
        *(float4*)dst       = h0;
        *(float4*)(dst + 4) = h1;
        float wrc = sWr[64 + c];
        rsum[0] += wrc * h0.x; rsum[1] += wrc * h0.y;
        rsum[2] += wrc * h0.z; rsum[3] += wrc * h0.w;
        rsum[4] += wrc * h1.x; rsum[5] += wrc * h1.y;
        rsum[6] += wrc * h1.z; rsum[7] += wrc * h1.w;
    }
#pragma unroll
    for (int j = 0; j < 8; ++j) sred[ty][n0 + j] = rsum[j];
    __syncthreads();
    if (t < 128) {
        float s = b_read[0];
#pragma unroll
        for (int k = 0; k < 8; ++k) s += sred[k][t];
        rd[b * N_ + v0 + t] = s;
    }
}

extern "C" void kernel_launch(void* const* d_in, const int* in_sizes, int n_in,
                              void* d_out, int out_size) {
    const float* x       = (const float*)d_in[0];
    const float* m       = (const float*)d_in[1];
    const float* u       = (const float*)d_in[2];
    const float* h       = (const float*)d_in[3];
    const float* adj     = (const float*)d_in[4];
    const float* W_in    = (const float*)d_in[5];
    const float* b_in    = (const float*)d_in[6];
    const float* W_gc    = (const float*)d_in[7];
    const float* b_gc    = (const float*)d_in[8];
    const float* W_out   = (const float*)d_in[9];
    const float* b_out   = (const float*)d_in[10];
    const float* W_read  = (const float*)d_in[11];
    const float* b_read  = (const float*)d_in[12];
    const float* prelu_w = (const float*)d_in[13];

    float* read_out = (float*)d_out;
    float* out_big  = (float*)d_out + READ_ELEMS;

    k0_combine<<<68, 128>>>(W_gc, W_in, b_in);
    k1_yin<<<dim3(N_ / 128, B_), 256>>>(x, m, u, h);
    k2_mma<<<dim3(N_ / 128, (B_ * DMX) / 128), 256>>>(adj, b_gc);
    k34_out<<<dim3(N_ / 128, B_), 128>>>(h, W_out, b_out, prelu_w,
                                         W_read, b_read, out_big, read_out);
}

// round 5
// speedup vs baseline: 1.9788x; 1.0328x over previous
#include <cuda_runtime.h>
#include <cstdint>

// Problem constants
#define B_   128
#define N_   1024
#define DMX  64
#define DIN  68
#define READ_ELEMS (B_ * N_)

// Scratch (device globals; no allocations allowed)
__device__ float g_C[2 * DMX * DIN];         // combined W_gc_s @ W_in : [s*64+o][d]
__device__ float g_cb[2 * DMX];              // combined bias
__device__ float g_Y[2u * B_ * DMX * N_];    // [s][r=b*64+o][v]  64 MB (tf32-rounded)
__device__ float g_Aj[2u * N_ * N_];         // tf32-rounded adj    8 MB
__device__ float g_G[(size_t)B_ * DMX * N_]; // [r=b*64+o][w]      32 MB

// ================= f32x2 packed-FMA helpers =================
__device__ __forceinline__ unsigned long long pk2(float v) {
    unsigned long long r;
    asm("mov.b64 %0, {%1, %1};" : "=l"(r) : "f"(v));
    return r;
}
__device__ __forceinline__ void ffma2(unsigned long long& d,
                                      unsigned long long a,
                                      unsigned long long b) {
    asm("fma.rn.f32x2 %0, %1, %2, %0;" : "+l"(d) : "l"(a), "l"(b));
}
__device__ __forceinline__ float2 upk2(unsigned long long v) {
    float2 r;
    asm("mov.b64 {%0, %1}, %2;" : "=f"(r.x), "=f"(r.y) : "l"(v));
    return r;
}

// ================= warp-level tf32 MMA helpers (base ISA, sm_80+) =================
__device__ __forceinline__ uint32_t f2tf32(float x) {
    uint32_t u;
    asm("cvt.rna.tf32.f32 %0, %1;" : "=r"(u) : "f"(x));
    return u;
}
__device__ __forceinline__ void mma16n8k8(float* c, const uint32_t* a, const uint32_t* b) {
    asm volatile(
        "mma.sync.aligned.m16n8k8.row.col.f32.tf32.tf32.f32 "
        "{%0,%1,%2,%3}, {%4,%5,%6,%7}, {%8,%9}, {%0,%1,%2,%3};"
        : "+f"(c[0]), "+f"(c[1]), "+f"(c[2]), "+f"(c[3])
        : "r"(a[0]), "r"(a[1]), "r"(a[2]), "r"(a[3]),
          "r"(b[0]), "r"(b[1]));
}

// ================= K0: fold W_gc into W_in =================
__global__ void k0_combine(const float* __restrict__ W_gc,
                           const float* __restrict__ W_in,
                           const float* __restrict__ b_in) {
    int d = blockIdx.x;          // 0..67
    int t = threadIdx.x;         // 0..127 -> (s,o)
    int s = t >> 6, o = t & 63;
    const float* wg = W_gc + o * 128 + s * 64;
    float acc = 0.f;
#pragma unroll 8
    for (int c = 0; c < 64; ++c) acc += wg[c] * W_in[c * DIN + d];
    g_C[t * DIN + d] = acc;
    if (d == 0) {
        float ab = 0.f;
        for (int c = 0; c < 64; ++c) ab += wg[c] * b_in[c];
        g_cb[t] = ab;
    }
}

// ================= Kadj: pre-round adj to tf32 =================
__global__ void k_adj(const float* __restrict__ adj) {
    size_t i = ((size_t)blockIdx.x * 256 + threadIdx.x) * 4;
    float4 v = *(const float4*)(adj + i);
    uint4 r;
    r.x = f2tf32(v.x); r.y = f2tf32(v.y); r.z = f2tf32(v.z); r.w = f2tf32(v.w);
    *(uint4*)(g_Aj + i) = r;
}

// ================= K1: Y = tf32_round(C @ cat(x,m,u,h) + cb) =================
__global__ void __launch_bounds__(256) k1_yin(const float* __restrict__ x,
                                              const float* __restrict__ m,
                                              const float* __restrict__ u,
                                              const float* __restrict__ h) {
    __shared__ float sA[34][136];   // [d][row]
    __shared__ float sB[34][136];   // [d][v]
    const int b  = blockIdx.y;
    const int v0 = blockIdx.x * 128;
    const int t  = threadIdx.x;
    const int ty = t >> 4, tx = t & 15;
    const int m0 = ty * 8, n0 = tx * 8;

    unsigned long long acc2[8][4];
#pragma unroll
    for (int i = 0; i < 8; ++i)
#pragma unroll
        for (int j = 0; j < 4; ++j) acc2[i][j] = 0ull;

    for (int kc = 0; kc < 2; ++kc) {
        const int d0 = kc * 34;
        for (int e = t; e < 34 * 128; e += 256) {
            int dd = e >> 7, so = e & 127;
            sA[dd][so] = g_C[so * DIN + d0 + dd];
        }
        for (int e = t; e < 34 * 128; e += 256) {
            int dd = e >> 7, vv = e & 127;
            int d = d0 + dd, v = v0 + vv;
            float val;
            if (d == 0)      val = x[b * N_ + v];
            else if (d == 1) val = m[b * N_ + v];
            else if (d < 4)  val = u[(b * 2 + (d - 2)) * N_ + v];
            else             val = h[((size_t)b * 64 + (d - 4)) * N_ + v];
            sB[dd][vv] = val;
        }
        __syncthreads();
#pragma unroll
        for (int dd = 0; dd < 34; ++dd) {
            float4 a0 = *(const float4*)&sA[dd][m0];
            float4 a1 = *(const float4*)&sA[dd][m0 + 4];
            ulonglong2 bq0 = *(const ulonglong2*)&sB[dd][n0];
            ulonglong2 bq1 = *(const ulonglong2*)&sB[dd][n0 + 4];
            unsigned long long av[8] = {pk2(a0.x), pk2(a0.y), pk2(a0.z), pk2(a0.w),
                                        pk2(a1.x), pk2(a1.y), pk2(a1.z), pk2(a1.w)};
            unsigned long long bv[4] = {bq0.x, bq0.y, bq1.x, bq1.y};
#pragma unroll
            for (int i = 0; i < 8; ++i)
#pragma unroll
                for (int j = 0; j < 4; ++j) ffma2(acc2[i][j], av[i], bv[j]);
        }
        __syncthreads();
    }
#pragma unroll
    for (int i = 0; i < 8; ++i) {
        int so = m0 + i;
        int s = so >> 6, o = so & 63;
        float bias = g_cb[so];
        uint32_t buf[8];
#pragma unroll
        for (int j = 0; j < 4; ++j) {
            float2 p = upk2(acc2[i][j]);
            buf[2 * j]     = f2tf32(p.x + bias);
            buf[2 * j + 1] = f2tf32(p.y + bias);
        }
        float* dst = &g_Y[(((size_t)s * B_ + b) * 64 + o) * N_ + v0 + n0];
        *(uint4*)dst       = *(uint4*)&buf[0];
        *(uint4*)(dst + 4) = *(uint4*)&buf[4];
    }
}

// ================= K2: warp-MMA tf32 NT GEMM (cvt-free, double-buffered) =================
// G[r][w] = b_gc[r&63] + sum_s sum_v Y_s[r][v] * adj_s[w][v]
// 128x128 CTA tile, BK=32, 8 warps of 64x32, fragment-major smem, 2 stages.
#define K2_SMEM_BYTES (2 * 8192 * 4)

__global__ void __launch_bounds__(256, 2) k2_mma(const float* __restrict__ b_gc) {
    extern __shared__ uint32_t S[];   // stage p: A at p*8192 (4096 u32), B at +4096
    const int t    = threadIdx.x;
    const int lane = t & 31, wid = t >> 5;
    const int wm = wid >> 2, wn = wid & 3;
    const int r0 = blockIdx.y * 128;
    const int w0 = blockIdx.x * 128;

    // Per-thread staging targets (constant across kc)
    int aidx[4], bidx[4], roff[4], coff[4];
#pragma unroll
    for (int q = 0; q < 4; ++q) {
        int f = t + q * 256;           // 0..1023
        int r = f >> 3;                // 0..127
        int c4 = (f & 7) * 4;          // 0..28
        int ks = c4 >> 3, th = (c4 >> 2) & 1;
        int mf = r >> 4, row_in = r & 15, g = row_in & 7, hi = row_in >> 3;
        aidx[q] = (((ks * 8 + mf) * 32) + g * 4) * 4 + hi + 2 * th;
        int nf = r >> 3, n_in = r & 7;
        bidx[q] = (((ks * 16 + nf) * 32) + n_in * 4) * 2 + th;
        roff[q] = r; coff[q] = c4;
    }

    float acc[4][4][4];
#pragma unroll
    for (int i = 0; i < 4; ++i)
#pragma unroll
        for (int j = 0; j < 4; ++j)
#pragma unroll
            for (int c = 0; c < 4; ++c) acc[i][j][c] = 0.f;

    // Prologue: stage kc=0 into stage 0
    {
        const float* Ab = g_Y + (size_t)r0 * N_;
        const float* Bb = g_Aj + (size_t)w0 * N_;
#pragma unroll
        for (int q = 0; q < 4; ++q) {
            uint4 v = *(const uint4*)(Ab + (size_t)roff[q] * N_ + coff[q]);
            uint32_t* bp = S + aidx[q];
            bp[0] = v.x; bp[4] = v.y; bp[8] = v.z; bp[12] = v.w;
        }
#pragma unroll
        for (int q = 0; q < 4; ++q) {
            uint4 v = *(const uint4*)(Bb + (size_t)roff[q] * N_ + coff[q]);
            uint32_t* bp = S + 4096 + bidx[q];
            bp[0] = v.x; bp[2] = v.y; bp[4] = v.z; bp[6] = v.w;
        }
    }
    __syncthreads();

    for (int kc = 0; kc < 64; ++kc) {
        const int p = kc & 1;
        uint4 apre[4];
        const float* BbN = nullptr;
        if (kc < 63) {
            const int kn = kc + 1;
            const int s  = kn >> 5;
            const int vc = (kn & 31) * 32;
            const float* AbN = g_Y + (size_t)s * (B_ * DMX * N_) + (size_t)r0 * N_ + vc;
            BbN = g_Aj + (size_t)s * (N_ * N_) + (size_t)w0 * N_ + vc;
#pragma unroll
            for (int q = 0; q < 4; ++q)
                apre[q] = *(const uint4*)(AbN + (size_t)roff[q] * N_ + coff[q]);
        }
        // Compute on stage p
        const uint32_t* SA = S + p * 8192;
        const uint32_t* SB = SA + 4096;
#pragma unroll
        for (int ks = 0; ks < 4; ++ks) {
            uint32_t af[4][4];
#pragma unroll
            for (int i = 0; i < 4; ++i) {
                uint4 v = *(const uint4*)&SA[((ks * 8 + wm * 4 + i) * 32 + lane) * 4];
                af[i][0] = v.x; af[i][1] = v.y; af[i][2] = v.z; af[i][3] = v.w;
            }
            uint32_t bf[4][2];
#pragma unroll
            for (int j = 0; j < 4; ++j) {
                uint2 v = *(const uint2*)&SB[((ks * 16 + wn * 4 + j) * 32 + lane) * 2];
                bf[j][0] = v.x; bf[j][1] = v.y;
            }
#pragma unroll
            for (int i = 0; i < 4; ++i)
#pragma unroll
                for (int j = 0; j < 4; ++j)
                    mma16n8k8(acc[i][j], af[i], bf[j]);
        }
        // Store next stage (p^1)
        if (kc < 63) {
            uint32_t* SAn = S + (p ^ 1) * 8192;
#pragma unroll
            for (int q = 0; q < 4; ++q) {
                uint32_t* bp = SAn + aidx[q];
                bp[0] = apre[q].x; bp[4] = apre[q].y; bp[8] = apre[q].z; bp[12] = apre[q].w;
            }
#pragma unroll
            for (int q = 0; q < 4; ++q) {
                uint4 v = *(const uint4*)(BbN + (size_t)roff[q] * N_ + coff[q]);
                uint32_t* bp = SAn + 4096 + bidx[q];
                bp[0] = v.x; bp[2] = v.y; bp[4] = v.z; bp[6] = v.w;
            }
        }
        __syncthreads();
    }

    // Epilogue: add bias, store
    const int g = lane >> 2, tq = lane & 3;
#pragma unroll
    for (int i = 0; i < 4; ++i) {
        const int rloc = wm * 64 + i * 16 + g;
        const float bias0 = b_gc[(rloc) & 63];
        const float bias1 = b_gc[(rloc + 8) & 63];
        float* row0 = &g_G[(size_t)(r0 + rloc) * N_ + w0 + wn * 32 + 2 * tq];
        float* row1 = row0 + 8 * N_;
#pragma unroll
        for (int j = 0; j < 4; ++j) {
            float2 v0 = {acc[i][j][0] + bias0, acc[i][j][1] + bias0};
            float2 v1 = {acc[i][j][2] + bias1, acc[i][j][3] + bias1};
            *(float2*)(row0 + j * 8) = v0;
            *(float2*)(row1 + j * 8) = v1;
        }
    }
}

// ================= K34: out-conv + PReLU + h-copy + fused readout =================
// 256 threads: ty 0..15 (o tile of 4), tx 0..15 (n tile of 8). Grid (N/128, B).
__global__ void __launch_bounds__(256) k34_out(const float* __restrict__ h,
                                               const float* __restrict__ W_out,
                                               const float* __restrict__ b_out,
                                               const float* __restrict__ prelu_w,
                                               const float* __restrict__ W_read,
                                               const float* __restrict__ b_read,
                                               float* __restrict__ out,
                                               float* __restrict__ rd) {
    __shared__ float sW[32][68];     // [k][o]
    __shared__ float sD[32][136];    // [k][n]
    __shared__ float sWr[128];
    __shared__ float sred[16][128];
    const int b  = blockIdx.y;
    const int v0 = blockIdx.x * 128;
    const int t  = threadIdx.x;
    const int ty = t >> 4, tx = t & 15;
    const int o0 = ty * 4, n0 = tx * 8;

    if (t < 128) sWr[t] = W_read[t];

    unsigned long long acc2[4][4];
#pragma unroll
    for (int i = 0; i < 4; ++i)
#pragma unroll
        for (int j = 0; j < 4; ++j) acc2[i][j] = 0ull;

    for (int kc = 0; kc < 4; ++kc) {
        const int k0 = kc * 32;
        for (int e = t; e < 32 * 64; e += 256) {
            int kk = e >> 6, o = e & 63;
            sW[kk][o] = W_out[o * 128 + k0 + kk];
        }
        for (int e = t; e < 32 * 128; e += 256) {
            int kk = e >> 7, vv = e & 127;
            int k = k0 + kk;
            sD[kk][vv] = (k < 64)
                ? g_G[((size_t)b * 64 + k) * N_ + v0 + vv]
                : h[((size_t)b * 64 + (k - 64)) * N_ + v0 + vv];
        }
        __syncthreads();
#pragma unroll
        for (int kk = 0; kk < 32; ++kk) {
            float4 a = *(const float4*)&sW[kk][o0];
            ulonglong2 bq0 = *(const ulonglong2*)&sD[kk][n0];
            ulonglong2 bq1 = *(const ulonglong2*)&sD[kk][n0 + 4];
            unsigned long long av[4] = {pk2(a.x), pk2(a.y), pk2(a.z), pk2(a.w)};
            unsigned long long bv[4] = {bq0.x, bq0.y, bq1.x, bq1.y};
#pragma unroll
            for (int i = 0; i < 4; ++i)
#pragma unroll
                for (int j = 0; j < 4; ++j) ffma2(acc2[i][j], av[i], bv[j]);
        }
        __syncthreads();
    }

    const float pw = prelu_w[0];
    float rsum[8];
#pragma unroll
    for (int j = 0; j < 8; ++j) rsum[j] = 0.f;

#pragma unroll
    for (int i = 0; i < 4; ++i) {
        int o = o0 + i;
        float bo = b_out[o];
        float wro = sWr[o];
        float buf[8];
#pragma unroll
        for (int j = 0; j < 4; ++j) {
            float2 p = upk2(acc2[i][j]);
            float v0f = p.x + bo; v0f = (v0f >= 0.f) ? v0f : pw * v0f;
            float v1f = p.y + bo; v1f = (v1f >= 0.f) ? v1f : pw * v1f;
            buf[2 * j] = v0f; buf[2 * j + 1] = v1f;
            rsum[2 * j]     += wro * v0f;
            rsum[2 * j + 1] += wro * v1f;
        }
        float* dst = &out[((size_t)b * 128 + o) * N_ + v0 + n0];
        *(float4*)dst       = *(float4*)&buf[0];
        *(float4*)(dst + 4) = *(float4*)&buf[4];
    }
    // h copy for channels [ty*4, ty*4+4), accumulate readout
#pragma unroll
    for (int i = 0; i < 4; ++i) {
        int c = ty * 4 + i;
        const float* src = &h[((size_t)b * 64 + c) * N_ + v0 + n0];
        float4 h0 = *(const float4*)src;
        float4 h1 = *(const float4*)(src + 4);
        float* dst = &out[((size_t)b * 128 + 64 + c) * N_ + v0 + n0];
        *(float4*)dst       = h0;
        *(float4*)(dst + 4) = h1;
        float wrc = sWr[64 + c];
        rsum[0] += wrc * h0.x; rsum[1] += wrc * h0.y;
        rsum[2] += wrc * h0.z; rsum[3] += wrc * h0.w;
        rsum[4] += wrc * h1.x; rsum[5] += wrc * h1.y;
        rsum[6] += wrc * h1.z; rsum[7] += wrc * h1.w;
    }
#pragma unroll
    for (int j = 0; j < 8; ++j) sred[ty][n0 + j] = rsum[j];
    __syncthreads();
    if (t < 128) {
        float s = b_read[0];
#pragma unroll
        for (int k = 0; k < 16; ++k) s += sred[k][t];
        rd[b * N_ + v0 + t] = s;
    }
}

extern "C" void kernel_launch(void* const* d_in, const int* in_sizes, int n_in,
                              void* d_out, int out_size) {
    const float* x       = (const float*)d_in[0];
    const float* m       = (const float*)d_in[1];
    const float* u       = (const float*)d_in[2];
    const float* h       = (const float*)d_in[3];
    const float* adj     = (const float*)d_in[4];
    const float* W_in    = (const float*)d_in[5];
    const float* b_in    = (const float*)d_in[6];
    const float* W_gc    = (const float*)d_in[7];
    const float* b_gc    = (const float*)d_in[8];
    const float* W_out   = (const float*)d_in[9];
    const float* b_out   = (const float*)d_in[10];
    const float* W_read  = (const float*)d_in[11];
    const float* b_read  = (const float*)d_in[12];
    const float* prelu_w = (const float*)d_in[13];

    float* read_out = (float*)d_out;
    float* out_big  = (float*)d_out + READ_ELEMS;

    static bool attr_set = false;
    if (!attr_set) {
        cudaFuncSetAttribute(k2_mma, cudaFuncAttributeMaxDynamicSharedMemorySize,
                             K2_SMEM_BYTES);
        attr_set = true;
    }

    k0_combine<<<68, 128>>>(W_gc, W_in, b_in);
    k_adj<<<2048, 256>>>(adj);
    k1_yin<<<dim3(N_ / 128, B_), 256>>>(x, m, u, h);
    k2_mma<<<dim3(N_ / 128, (B_ * DMX) / 128), 256, K2_SMEM_BYTES>>>(b_gc);
    k34_out<<<dim3(N_ / 128, B_), 256>>>(h, W_out, b_out, prelu_w,
                                         W_read, b_read, out_big, read_out);
}

// round 7
// speedup vs baseline: 2.7495x; 1.3895x over previous
#include <cuda_runtime.h>
#include <cstdint>

// Problem constants
#define B_   128
#define N_   1024
#define DMX  64
#define DIN  68
#define READ_ELEMS (B_ * N_)

// Scratch (device globals; no allocations allowed)
__device__ float    g_C[2 * DMX * DIN];              // combined W_gc_s @ W_in
__device__ float    g_cb[2 * DMX];                   // combined bias
__device__ uint32_t g_Yb[2u * B_ * DMX * N_ / 2];    // bf16x2-packed Y  32 MB
__device__ uint32_t g_Ab[2u * N_ * N_ / 2];          // bf16x2-packed adj 4 MB
__device__ float    g_G[(size_t)B_ * DMX * N_];      // gc result        32 MB

// ================= f32x2 packed-FMA helpers =================
__device__ __forceinline__ unsigned long long pk2(float v) {
    unsigned long long r;
    asm("mov.b64 %0, {%1, %1};" : "=l"(r) : "f"(v));
    return r;
}
__device__ __forceinline__ void ffma2(unsigned long long& d,
                                      unsigned long long a,
                                      unsigned long long b) {
    asm("fma.rn.f32x2 %0, %1, %2, %0;" : "+l"(d) : "l"(a), "l"(b));
}
__device__ __forceinline__ float2 upk2(unsigned long long v) {
    float2 r;
    asm("mov.b64 {%0, %1}, %2;" : "=f"(r.x), "=f"(r.y) : "l"(v));
    return r;
}

// ================= bf16 helpers =================
__device__ __forceinline__ uint32_t pack_bf16x2(float lo, float hi) {
    uint32_t r;
    asm("cvt.rn.bf16x2.f32 %0, %1, %2;" : "=r"(r) : "f"(hi), "f"(lo));
    return r;
}
// bf16 m16n8k16 (base ISA, sm_80+)
__device__ __forceinline__ void mma_bf16(float* c, const uint32_t* a, const uint32_t* b) {
    asm volatile(
        "mma.sync.aligned.m16n8k16.row.col.f32.bf16.bf16.f32 "
        "{%0,%1,%2,%3}, {%4,%5,%6,%7}, {%8,%9}, {%0,%1,%2,%3};"
        : "+f"(c[0]), "+f"(c[1]), "+f"(c[2]), "+f"(c[3])
        : "r"(a[0]), "r"(a[1]), "r"(a[2]), "r"(a[3]),
          "r"(b[0]), "r"(b[1]));
}

// ================= K0: fold W_gc into W_in =================
__global__ void k0_combine(const float* __restrict__ W_gc,
                           const float* __restrict__ W_in,
                           const float* __restrict__ b_in) {
    int d = blockIdx.x;          // 0..67
    int t = threadIdx.x;         // 0..127 -> (s,o)
    int s = t >> 6, o = t & 63;
    const float* wg = W_gc + o * 128 + s * 64;
    float acc = 0.f;
#pragma unroll 8
    for (int c = 0; c < 64; ++c) acc += wg[c] * W_in[c * DIN + d];
    g_C[t * DIN + d] = acc;
    if (d == 0) {
        float ab = 0.f;
        for (int c = 0; c < 64; ++c) ab += wg[c] * b_in[c];
        g_cb[t] = ab;
    }
}

// ================= Kadj: pack adj to bf16x2 =================
__global__ void k_adj(const float* __restrict__ adj) {
    size_t i = ((size_t)blockIdx.x * 256 + threadIdx.x) * 8;
    float4 v0 = *(const float4*)(adj + i);
    float4 v1 = *(const float4*)(adj + i + 4);
    uint4 r;
    r.x = pack_bf16x2(v0.x, v0.y);
    r.y = pack_bf16x2(v0.z, v0.w);
    r.z = pack_bf16x2(v1.x, v1.y);
    r.w = pack_bf16x2(v1.z, v1.w);
    *(uint4*)(g_Ab + i / 2) = r;
}

// ================= K1: Y = bf16(C @ cat(x,m,u,h) + cb) =================
__global__ void __launch_bounds__(256) k1_yin(const float* __restrict__ x,
                                              const float* __restrict__ m,
                                              const float* __restrict__ u,
                                              const float* __restrict__ h) {
    __shared__ float sA[34][136];   // [d][row]
    __shared__ float sB[34][136];   // [d][v]
    const int b  = blockIdx.y;
    const int v0 = blockIdx.x * 128;
    const int t  = threadIdx.x;
    const int ty = t >> 4, tx = t & 15;
    const int m0 = ty * 8, n0 = tx * 8;

    unsigned long long acc2[8][4];
#pragma unroll
    for (int i = 0; i < 8; ++i)
#pragma unroll
        for (int j = 0; j < 4; ++j) acc2[i][j] = 0ull;

    for (int kc = 0; kc < 2; ++kc) {
        const int d0 = kc * 34;
        for (int e = t; e < 34 * 128; e += 256) {
            int dd = e >> 7, so = e & 127;
            sA[dd][so] = g_C[so * DIN + d0 + dd];
        }
        for (int e = t; e < 34 * 128; e += 256) {
            int dd = e >> 7, vv = e & 127;
            int d = d0 + dd, v = v0 + vv;
            float val;
            if (d == 0)      val = x[b * N_ + v];
            else if (d == 1) val = m[b * N_ + v];
            else if (d < 4)  val = u[(b * 2 + (d - 2)) * N_ + v];
            else             val = h[((size_t)b * 64 + (d - 4)) * N_ + v];
            sB[dd][vv] = val;
        }
        __syncthreads();
#pragma unroll
        for (int dd = 0; dd < 34; ++dd) {
            float4 a0 = *(const float4*)&sA[dd][m0];
            float4 a1 = *(const float4*)&sA[dd][m0 + 4];
            ulonglong2 bq0 = *(const ulonglong2*)&sB[dd][n0];
            ulonglong2 bq1 = *(const ulonglong2*)&sB[dd][n0 + 4];
            unsigned long long av[8] = {pk2(a0.x), pk2(a0.y), pk2(a0.z), pk2(a0.w),
                                        pk2(a1.x), pk2(a1.y), pk2(a1.z), pk2(a1.w)};
            unsigned long long bv[4] = {bq0.x, bq0.y, bq1.x, bq1.y};
#pragma unroll
            for (int i = 0; i < 8; ++i)
#pragma unroll
                for (int j = 0; j < 4; ++j) ffma2(acc2[i][j], av[i], bv[j]);
        }
        __syncthreads();
    }
#pragma unroll
    for (int i = 0; i < 8; ++i) {
        int so = m0 + i;
        int s = so >> 6, o = so & 63;
        float bias = g_cb[so];
        uint32_t buf[4];
#pragma unroll
        for (int j = 0; j < 4; ++j) {
            float2 p = upk2(acc2[i][j]);
            buf[j] = pack_bf16x2(p.x + bias, p.y + bias);
        }
        uint32_t* dst = &g_Yb[(((size_t)s * B_ + b) * 64 + o) * (N_ / 2) + (v0 + n0) / 2];
        *(uint4*)dst = *(uint4*)&buf[0];
    }
}

// ================= K2: warp-MMA bf16 NT GEMM (double-buffered) =================
// G[r][w] = b_gc[r&63] + sum_s sum_v Y_s[r][v] * adj_s[w][v]
// 128x128 CTA tile, BK=32 (2 x k16), 8 warps of 64x32, fragment-major smem.
// Stage: A 2048 u32 (8 KB) + B 2048 u32 (8 KB); 2 stages = 32 KB static.
__global__ void __launch_bounds__(256, 2) k2_mma(const float* __restrict__ b_gc) {
    __shared__ uint32_t S[2 * 4096];
    const int t    = threadIdx.x;
    const int lane = t & 31, wid = t >> 5;
    const int wm = wid >> 2, wn = wid & 3;
    const int r0 = blockIdx.y * 128;
    const int w0 = blockIdx.x * 128;

    // Per-thread staging targets (2 quanta of uint4 = 4 bf16-pairs each)
    int aidx[2], bidx[2], goff[2];
#pragma unroll
    for (int q = 0; q < 2; ++q) {
        int f  = t + q * 256;          // 0..511
        int r  = f >> 2;               // 0..127
        int pq = f & 3;                // which 4-pair group (pairs 4pq..4pq+3)
        int ks = pq >> 1;              // which k16 chunk
        int u  = pq & 1;               // pair-group within chunk (0: p0..3, 1: p4..7)
        // A fragment coords
        int mf = r >> 4, row_in = r & 15, g = row_in & 7, hi = row_in >> 3;
        aidx[q] = (((ks * 8 + mf) * 32) + g * 4) * 4 + (2 * u + hi);
        // B fragment coords
        int nf = r >> 3, n_in = r & 7;
        bidx[q] = (((ks * 16 + nf) * 32) + n_in * 4) * 2 + u;
        goff[q] = r * (N_ / 2) + pq * 4;   // u32 offset in gmem tile
    }

    float acc[4][4][4];
#pragma unroll
    for (int i = 0; i < 4; ++i)
#pragma unroll
        for (int j = 0; j < 4; ++j)
#pragma unroll
            for (int c = 0; c < 4; ++c) acc[i][j][c] = 0.f;

    // Prologue: stage kc=0 into stage 0
    {
        const uint32_t* Ag = g_Yb + (size_t)r0 * (N_ / 2);
        const uint32_t* Bg = g_Ab + (size_t)w0 * (N_ / 2);
#pragma unroll
        for (int q = 0; q < 2; ++q) {
            uint4 v = *(const uint4*)(Ag + goff[q]);
            uint32_t* bp = S + aidx[q];
            bp[0] = v.x; bp[4] = v.y; bp[8] = v.z; bp[12] = v.w;
            uint4 w = *(const uint4*)(Bg + goff[q]);
            uint32_t* cp = S + 2048 + bidx[q];
            cp[0] = w.x; cp[2] = w.y; cp[4] = w.z; cp[6] = w.w;
        }
    }
    __syncthreads();

    for (int kc = 0; kc < 64; ++kc) {
        const int p = kc & 1;
        uint4 apre[2];
        const uint32_t* BgN = nullptr;
        if (kc < 63) {
            const int kn = kc + 1;
            const int s  = kn >> 5;
            const int vc = (kn & 31) * 16;   // pair offset
            const uint32_t* AgN = g_Yb + (size_t)s * (B_ * DMX * N_ / 2)
                                       + (size_t)r0 * (N_ / 2) + vc;
            BgN = g_Ab + (size_t)s * (N_ * N_ / 2) + (size_t)w0 * (N_ / 2) + vc;
#pragma unroll
            for (int q = 0; q < 2; ++q)
                apre[q] = *(const uint4*)(AgN + goff[q]);
        }
        // Compute on stage p
        const uint32_t* SA = S + p * 4096;
        const uint32_t* SB = SA + 2048;
#pragma unroll
        for (int ks = 0; ks < 2; ++ks) {
            uint32_t af[4][4];
#pragma unroll
            for (int i = 0; i < 4; ++i) {
                uint4 v = *(const uint4*)&SA[((ks * 8 + wm * 4 + i) * 32 + lane) * 4];
                af[i][0] = v.x; af[i][1] = v.y; af[i][2] = v.z; af[i][3] = v.w;
            }
            uint32_t bf[4][2];
#pragma unroll
            for (int j = 0; j < 4; ++j) {
                uint2 v = *(const uint2*)&SB[((ks * 16 + wn * 4 + j) * 32 + lane) * 2];
                bf[j][0] = v.x; bf[j][1] = v.y;
            }
#pragma unroll
            for (int i = 0; i < 4; ++i)
#pragma unroll
                for (int j = 0; j < 4; ++j)
                    mma_bf16(acc[i][j], af[i], bf[j]);
        }
        // Store next stage
        if (kc < 63) {
            uint32_t* SAn = S + ((p ^ 1) * 4096);
#pragma unroll
            for (int q = 0; q < 2; ++q) {
                uint32_t* bp = SAn + aidx[q];
                bp[0] = apre[q].x; bp[4] = apre[q].y; bp[8] = apre[q].z; bp[12] = apre[q].w;
                uint4 w = *(const uint4*)(BgN + goff[q]);
                uint32_t* cp = SAn + 2048 + bidx[q];
                cp[0] = w.x; cp[2] = w.y; cp[4] = w.z; cp[6] = w.w;
            }
        }
        __syncthreads();
    }

    // Epilogue: add bias, store
    const int g = lane >> 2, tq = lane & 3;
#pragma unroll
    for (int i = 0; i < 4; ++i) {
        const int rloc = wm * 64 + i * 16 + g;
        const float bias0 = b_gc[(rloc) & 63];
        const float bias1 = b_gc[(rloc + 8) & 63];
        float* row0 = &g_G[(size_t)(r0 + rloc) * N_ + w0 + wn * 32 + 2 * tq];
        float* row1 = row0 + 8 * N_;
#pragma unroll
        for (int j = 0; j < 4; ++j) {
            float2 v0 = {acc[i][j][0] + bias0, acc[i][j][1] + bias0};
            float2 v1 = {acc[i][j][2] + bias1, acc[i][j][3] + bias1};
            *(float2*)(row0 + j * 8) = v0;
            *(float2*)(row1 + j * 8) = v1;
        }
    }
}

// ================= K34: out-conv + PReLU + h-copy + fused readout =================
__global__ void __launch_bounds__(256) k34_out(const float* __restrict__ h,
                                               const float* __restrict__ W_out,
                                               const float* __restrict__ b_out,
                                               const float* __restrict__ prelu_w,
                                               const float* __restrict__ W_read,
                                               const float* __restrict__ b_read,
                                               float* __restrict__ out,
                                               float* __restrict__ rd) {
    __shared__ float sW[32][68];     // [k][o]
    __shared__ float sD[32][136];    // [k][n]
    __shared__ float sWr[128];
    __shared__ float sred[16][128];
    const int b  = blockIdx.y;
    const int v0 = blockIdx.x * 128;
    const int t  = threadIdx.x;
    const int ty = t >> 4, tx = t & 15;
    const int o0 = ty * 4, n0 = tx * 8;

    if (t < 128) sWr[t] = W_read[t];

    unsigned long long acc2[4][4];
#pragma unroll
    for (int i = 0; i < 4; ++i)
#pragma unroll
        for (int j = 0; j < 4; ++j) acc2[i][j] = 0ull;

    for (int kc = 0; kc < 4; ++kc) {
        const int k0 = kc * 32;
        for (int e = t; e < 32 * 64; e += 256) {
            int kk = e >> 6, o = e & 63;
            sW[kk][o] = W_out[o * 128 + k0 + kk];
        }
        for (int e = t; e < 32 * 128; e += 256) {
            int kk = e >> 7, vv = e & 127;
            int k = k0 + kk;
            sD[kk][vv] = (k < 64)
                ? g_G[((size_t)b * 64 + k) * N_ + v0 + vv]
                : h[((size_t)b * 64 + (k - 64)) * N_ + v0 + vv];
        }
        __syncthreads();
#pragma unroll
        for (int kk = 0; kk < 32; ++kk) {
            float4 a = *(const float4*)&sW[kk][o0];
            ulonglong2 bq0 = *(const ulonglong2*)&sD[kk][n0];
            ulonglong2 bq1 = *(const ulonglong2*)&sD[kk][n0 + 4];
            unsigned long long av[4] = {pk2(a.x), pk2(a.y), pk2(a.z), pk2(a.w)};
            unsigned long long bv[4] = {bq0.x, bq0.y, bq1.x, bq1.y};
#pragma unroll
            for (int i = 0; i < 4; ++i)
#pragma unroll
                for (int j = 0; j < 4; ++j) ffma2(acc2[i][j], av[i], bv[j]);
        }
        __syncthreads();
    }

    const float pw = prelu_w[0];
    float rsum[8];
#pragma unroll
    for (int j = 0; j < 8; ++j) rsum[j] = 0.f;

#pragma unroll
    for (int i = 0; i < 4; ++i) {
        int o = o0 + i;
        float bo = b_out[o];
        float wro = sWr[o];
        float buf[8];
#pragma unroll
        for (int j = 0; j < 4; ++j) {
            float2 p = upk2(acc2[i][j]);
            float v0f = p.x + bo; v0f = (v0f >= 0.f) ? v0f : pw * v0f;
            float v1f = p.y + bo; v1f = (v1f >= 0.f) ? v1f : pw * v1f;
            buf[2 * j] = v0f; buf[2 * j + 1] = v1f;
            rsum[2 * j]     += wro * v0f;
            rsum[2 * j + 1] += wro * v1f;
        }
        float* dst = &out[((size_t)b * 128 + o) * N_ + v0 + n0];
        *(float4*)dst       = *(float4*)&buf[0];
        *(float4*)(dst + 4) = *(float4*)&buf[4];
    }
#pragma unroll
    for (int i = 0; i < 4; ++i) {
        int c = ty * 4 + i;
        const float* src = &h[((size_t)b * 64 + c) * N_ + v0 + n0];
        float4 h0 = *(const float4*)src;
        float4 h1 = *(const float4*)(src + 4);
        float* dst = &out[((size_t)b * 128 + 64 + c) * N_ + v0 + n0];
        *(float4*)dst       = h0;
        *(float4*)(dst + 4) = h1;
        float wrc = sWr[64 + c];
        rsum[0] += wrc * h0.x; rsum[1] += wrc * h0.y;
        rsum[2] += wrc * h0.z; rsum[3] += wrc * h0.w;
        rsum[4] += wrc * h1.x; rsum[5] += wrc * h1.y;
        rsum[6] += wrc * h1.z; rsum[7] += wrc * h1.w;
    }
#pragma unroll
    for (int j = 0; j < 8; ++j) sred[ty][n0 + j] = rsum[j];
    __syncthreads();
    if (t < 128) {
        float s = b_read[0];
#pragma unroll
        for (int k = 0; k < 16; ++k) s += sred[k][t];
        rd[b * N_ + v0 + t] = s;
    }
}

extern "C" void kernel_launch(void* const* d_in, const int* in_sizes, int n_in,
                              void* d_out, int out_size) {
    const float* x       = (const float*)d_in[0];
    const float* m       = (const float*)d_in[1];
    const float* u       = (const float*)d_in[2];
    const float* h       = (const float*)d_in[3];
    const float* adj     = (const float*)d_in[4];
    const float* W_in    = (const float*)d_in[5];
    const float* b_in    = (const float*)d_in[6];
    const float* W_gc    = (const float*)d_in[7];
    const float* b_gc    = (const float*)d_in[8];
    const float* W_out   = (const float*)d_in[9];
    const float* b_out   = (const float*)d_in[10];
    const float* W_read  = (const float*)d_in[11];
    const float* b_read  = (const float*)d_in[12];
    const float* prelu_w = (const float*)d_in[13];

    float* read_out = (float*)d_out;
    float* out_big  = (float*)d_out + READ_ELEMS;

    k0_combine<<<68, 128>>>(W_gc, W_in, b_in);
    k_adj<<<1024, 256>>>(adj);
    k1_yin<<<dim3(N_ / 128, B_), 256>>>(x, m, u, h);
    k2_mma<<<dim3(N_ / 128, (B_ * DMX) / 128), 256>>>(b_gc);
    k34_out<<<dim3(N_ / 128, B_), 256>>>(h, W_out, b_out, prelu_w,
                                         W_read, b_read, out_big, read_out);
}

// round 8
// speedup vs baseline: 3.8338x; 1.3944x over previous
#include <cuda_runtime.h>
#include <cstdint>

// Problem constants
#define B_   128
#define N_   1024
#define DMX  64
#define DIN  68
#define READ_ELEMS (B_ * N_)

// Scratch (device globals; no allocations allowed)
__device__ float    g_C[2 * DMX * DIN];            // combined W_gc_s @ W_in
__device__ float    g_cb[2 * DMX];                 // combined bias
__device__ uint32_t g_Af[2 * 64 * 64 * 128];       // adj A-fragments (bf16)  4 MB
__device__ uint32_t g_Yf[2u * 1024 * 64 * 64];     // Y   B-fragments (bf16) 33.5 MB
__device__ float    g_G[(size_t)B_ * DMX * N_];    // gc result 32 MB

// ================= f32x2 packed-FMA helpers =================
__device__ __forceinline__ unsigned long long pk2(float v) {
    unsigned long long r;
    asm("mov.b64 %0, {%1, %1};" : "=l"(r) : "f"(v));
    return r;
}
__device__ __forceinline__ unsigned long long pkpair(float lo, float hi) {
    unsigned long long r;
    asm("mov.b64 %0, {%1, %2};" : "=l"(r) : "f"(lo), "f"(hi));
    return r;
}
__device__ __forceinline__ void ffma2(unsigned long long& d,
                                      unsigned long long a,
                                      unsigned long long b) {
    asm("fma.rn.f32x2 %0, %1, %2, %0;" : "+l"(d) : "l"(a), "l"(b));
}
__device__ __forceinline__ float2 upk2(unsigned long long v) {
    float2 r;
    asm("mov.b64 {%0, %1}, %2;" : "=f"(r.x), "=f"(r.y) : "l"(v));
    return r;
}

// ================= bf16 helpers =================
__device__ __forceinline__ uint32_t pack_bf16x2(float lo, float hi) {
    uint32_t r;
    asm("cvt.rn.bf16x2.f32 %0, %1, %2;" : "=r"(r) : "f"(hi), "f"(lo));
    return r;
}
__device__ __forceinline__ void mma_bf16(float* c, const uint32_t* a, const uint32_t* b) {
    asm volatile(
        "mma.sync.aligned.m16n8k16.row.col.f32.bf16.bf16.f32 "
        "{%0,%1,%2,%3}, {%4,%5,%6,%7}, {%8,%9}, {%0,%1,%2,%3};"
        : "+f"(c[0]), "+f"(c[1]), "+f"(c[2]), "+f"(c[3])
        : "r"(a[0]), "r"(a[1]), "r"(a[2]), "r"(a[3]),
          "r"(b[0]), "r"(b[1]));
}

// ================= K0: fold W_gc into W_in =================
__global__ void k0_combine(const float* __restrict__ W_gc,
                           const float* __restrict__ W_in,
                           const float* __restrict__ b_in) {
    int d = blockIdx.x;          // 0..67
    int t = threadIdx.x;         // 0..127 -> (s,o)
    int s = t >> 6, o = t & 63;
    const float* wg = W_gc + o * 128 + s * 64;
    float acc = 0.f;
#pragma unroll 8
    for (int c = 0; c < 64; ++c) acc += wg[c] * W_in[c * DIN + d];
    g_C[t * DIN + d] = acc;
    if (d == 0) {
        float ab = 0.f;
        for (int c = 0; c < 64; ++c) ab += wg[c] * b_in[c];
        g_cb[t] = ab;
    }
}

// ================= k_adjf: repack adj into m16k16 A-fragments =================
// frag (s, mf, kc): lane l (g=l>>2, p=l&3) holds
//   a0=(row g, k 2p..2p+1)  a1=(row g+8, same)  a2=(row g, k+8)  a3=(row g+8, k+8)
__global__ void k_adjf(const float* __restrict__ adj) {
    int wg   = blockIdx.x * 8 + (threadIdx.x >> 5);   // 0..8191
    int lane = threadIdx.x & 31;
    int s  = wg >> 12;
    int mf = (wg >> 6) & 63;
    int kc = wg & 63;
    int g = lane >> 2, p = lane & 3;
    const float* rp = adj + ((size_t)(s * N_ + mf * 16 + g)) * N_ + kc * 16 + 2 * p;
    float2 v00 = *(const float2*)rp;
    float2 v10 = *(const float2*)(rp + 8 * N_);
    float2 v01 = *(const float2*)(rp + 8);
    float2 v11 = *(const float2*)(rp + 8 * N_ + 8);
    uint4 o;
    o.x = pack_bf16x2(v00.x, v00.y);
    o.y = pack_bf16x2(v10.x, v10.y);
    o.z = pack_bf16x2(v01.x, v01.y);
    o.w = pack_bf16x2(v11.x, v11.y);
    *(uint4*)&g_Af[(size_t)wg * 128 + lane * 4] = o;
}

// ================= K1: Y = bf16(C @ cat(x,m,u,h) + cb), scattered to B-frags =================
// B-frag (s, nf, kc): lane l (n_in=l>>2, p=l&3) holds
//   b0 = (row nf*8+n_in, k 2p..2p+1),  b1 = (same row, k 2p+8..2p+9)
__global__ void __launch_bounds__(256) k1_yin(const float* __restrict__ x,
                                              const float* __restrict__ m,
                                              const float* __restrict__ u,
                                              const float* __restrict__ h) {
    __shared__ float sA[34][136];   // [d][row]
    __shared__ float sB[34][136];   // [d][v]
    const int b  = blockIdx.y;
    const int v0 = blockIdx.x * 128;
    const int t  = threadIdx.x;
    const int ty = t >> 4, tx = t & 15;
    const int m0 = ty * 8, n0 = tx * 8;

    unsigned long long acc2[8][4];
#pragma unroll
    for (int i = 0; i < 8; ++i)
#pragma unroll
        for (int j = 0; j < 4; ++j) acc2[i][j] = 0ull;

    for (int kc = 0; kc < 2; ++kc) {
        const int d0 = kc * 34;
        for (int e = t; e < 34 * 128; e += 256) {
            int dd = e >> 7, so = e & 127;
            sA[dd][so] = g_C[so * DIN + d0 + dd];
        }
        for (int e = t; e < 34 * 128; e += 256) {
            int dd = e >> 7, vv = e & 127;
            int d = d0 + dd, v = v0 + vv;
            float val;
            if (d == 0)      val = x[b * N_ + v];
            else if (d == 1) val = m[b * N_ + v];
            else if (d < 4)  val = u[(b * 2 + (d - 2)) * N_ + v];
            else             val = h[((size_t)b * 64 + (d - 4)) * N_ + v];
            sB[dd][vv] = val;
        }
        __syncthreads();
#pragma unroll
        for (int dd = 0; dd < 34; ++dd) {
            float4 a0 = *(const float4*)&sA[dd][m0];
            float4 a1 = *(const float4*)&sA[dd][m0 + 4];
            ulonglong2 bq0 = *(const ulonglong2*)&sB[dd][n0];
            ulonglong2 bq1 = *(const ulonglong2*)&sB[dd][n0 + 4];
            unsigned long long av[8] = {pk2(a0.x), pk2(a0.y), pk2(a0.z), pk2(a0.w),
                                        pk2(a1.x), pk2(a1.y), pk2(a1.z), pk2(a1.w)};
            unsigned long long bv[4] = {bq0.x, bq0.y, bq1.x, bq1.y};
#pragma unroll
            for (int i = 0; i < 8; ++i)
#pragma unroll
                for (int j = 0; j < 4; ++j) ffma2(acc2[i][j], av[i], bv[j]);
        }
        __syncthreads();
    }
    // scatter epilogue into fragment layout
#pragma unroll
    for (int i = 0; i < 8; ++i) {
        int so = m0 + i;
        int s = so >> 6, o = so & 63;
        int r = b * 64 + o;
        int nf = r >> 3, n_in = r & 7;
        float bias = g_cb[so];
        uint32_t fbase = ((uint32_t)(s * 1024 + nf)) * 64 * 64;   // + kc*64 + lane*2 + reg
#pragma unroll
        for (int j = 0; j < 4; ++j) {
            float2 pr = upk2(acc2[i][j]);
            uint32_t val = pack_bf16x2(pr.x + bias, pr.y + bias);
            int J  = (v0 >> 1) + tx * 4 + j;     // global k-pair index 0..511
            int kc = J >> 3;
            int pp = J & 7;
            int reg = pp >> 2, p = pp & 3;
            g_Yf[fbase + kc * 64 + (n_in * 4 + p) * 2 + reg] = val;
        }
    }
}

// ================= K2: fragment-direct bf16 MMA GEMM (no smem staging) =================
// C[w][r] = sum_v adj[w][v] * Y[r][v]  ->  G[r][w] (+bias) via smem-transpose epilogue.
__global__ void __launch_bounds__(256, 2) k2_mma(const float* __restrict__ b_gc) {
    __shared__ float sT[128 * 68];
    const int t = threadIdx.x, lane = t & 31, wid = t >> 5;
    const int wm = wid >> 2, wn = wid & 3;
    const int w0 = blockIdx.x * 128;
    const int r0 = blockIdx.y * 128;

    const uint32_t* aBase = g_Af + (size_t)((w0 >> 4) + wm * 4) * (64 * 128) + lane * 4;
    const uint32_t* bBase = g_Yf + (size_t)((r0 >> 3) + wn * 4) * (64 * 64) + lane * 2;

    float acc[4][4][4];
#pragma unroll
    for (int i = 0; i < 4; ++i)
#pragma unroll
        for (int j = 0; j < 4; ++j)
#pragma unroll
            for (int c = 0; c < 4; ++c) acc[i][j][c] = 0.f;

    uint4 Ab[2][4];
    uint2 Bb[2][4];
#pragma unroll
    for (int i = 0; i < 4; ++i) Ab[0][i] = *(const uint4*)(aBase + i * 8192);
#pragma unroll
    for (int j = 0; j < 4; ++j) Bb[0][j] = *(const uint2*)(bBase + j * 4096);

    for (int kc = 0; kc < 128; ++kc) {
        const int cur = kc & 1;
        if (kc < 127) {
            const int kn = kc + 1;
            const uint32_t* ap = aBase + (kn >> 6) * (64 * 64 * 128) + (kn & 63) * 128;
            const uint32_t* bp = bBase + (kn >> 6) * (1024 * 64 * 64) + (kn & 63) * 64;
#pragma unroll
            for (int i = 0; i < 4; ++i) Ab[cur ^ 1][i] = *(const uint4*)(ap + i * 8192);
#pragma unroll
            for (int j = 0; j < 4; ++j) Bb[cur ^ 1][j] = *(const uint2*)(bp + j * 4096);
        }
#pragma unroll
        for (int i = 0; i < 4; ++i)
#pragma unroll
            for (int j = 0; j < 4; ++j)
                mma_bf16(acc[i][j], (const uint32_t*)&Ab[cur][i],
                         (const uint32_t*)&Bb[cur][j]);
    }

    // Epilogue: transpose through smem, add bias, store coalesced
    const int g = lane >> 2, tq = lane & 3;
    for (int p = 0; p < 2; ++p) {
        __syncthreads();
        if (wm == p) {
#pragma unroll
            for (int i = 0; i < 4; ++i) {
                int wl = i * 16 + g;
#pragma unroll
                for (int j = 0; j < 4; ++j) {
                    int rl = wn * 32 + j * 8 + 2 * tq;
                    sT[rl * 68 + wl]           = acc[i][j][0];
                    sT[(rl + 1) * 68 + wl]     = acc[i][j][1];
                    sT[rl * 68 + wl + 8]       = acc[i][j][2];
                    sT[(rl + 1) * 68 + wl + 8] = acc[i][j][3];
                }
            }
        }
        __syncthreads();
        for (int e = t; e < 128 * 16; e += 256) {
            int rl = e >> 4, c4 = (e & 15) * 4;
            float4 v = *(const float4*)&sT[rl * 68 + c4];
            float bias = b_gc[(r0 + rl) & 63];
            v.x += bias; v.y += bias; v.z += bias; v.w += bias;
            *(float4*)&g_G[(size_t)(r0 + rl) * N_ + w0 + p * 64 + c4] = v;
        }
    }
}

// ================= K34: register-resident out-conv + PReLU + h-copy + readout =================
// 256 thr: og = t&3 owns o-range og*16..+15 (8 f32x2 pairs); nq = t>>2 owns 4 nodes.
__global__ void __launch_bounds__(256) k34_out(const float* __restrict__ h,
                                               const float* __restrict__ W_out,
                                               const float* __restrict__ b_out,
                                               const float* __restrict__ prelu_w,
                                               const float* __restrict__ W_read,
                                               const float* __restrict__ b_read,
                                               float* __restrict__ out,
                                               float* __restrict__ rd) {
    __shared__ unsigned long long sW[128 * 32];   // [k][o-pair]
    __shared__ float sWr2[64];                    // W_read[64..127]
    const int b  = blockIdx.y;
    const int nb = blockIdx.x * 256;
    const int t  = threadIdx.x;
    const int og = t & 3;
    const int n0 = nb + (t >> 2) * 4;

    for (int e = t; e < 4096; e += 256) {
        int k = e >> 5, op = e & 31;
        float lo = W_out[(2 * op) * 128 + k];
        float hi = W_out[(2 * op + 1) * 128 + k];
        sW[k * 32 + op] = pkpair(lo, hi);
    }
    if (t < 64) sWr2[t] = W_read[64 + t];
    __syncthreads();

    unsigned long long acc[4][8];
#pragma unroll
    for (int n = 0; n < 4; ++n)
#pragma unroll
        for (int j = 0; j < 8; ++j) acc[n][j] = 0ull;
    float rsum[4] = {0.f, 0.f, 0.f, 0.f};

    // k = 0..63 : gc channels from g_G
#pragma unroll 4
    for (int k = 0; k < 64; ++k) {
        float4 v = *(const float4*)&g_G[((size_t)b * 64 + k) * N_ + n0];
        unsigned long long pv0 = pk2(v.x), pv1 = pk2(v.y), pv2 = pk2(v.z), pv3 = pk2(v.w);
#pragma unroll
        for (int j = 0; j < 8; ++j) {
            unsigned long long wv = sW[k * 32 + og * 8 + j];
            ffma2(acc[0][j], pv0, wv);
            ffma2(acc[1][j], pv1, wv);
            ffma2(acc[2][j], pv2, wv);
            ffma2(acc[3][j], pv3, wv);
        }
    }
    // k = 64..127 : h channels (+ copy + h-readout for c%4==og)
#pragma unroll 4
    for (int c = 0; c < 64; ++c) {
        float4 v = *(const float4*)&h[((size_t)b * 64 + c) * N_ + n0];
        unsigned long long pv0 = pk2(v.x), pv1 = pk2(v.y), pv2 = pk2(v.z), pv3 = pk2(v.w);
#pragma unroll
        for (int j = 0; j < 8; ++j) {
            unsigned long long wv = sW[(64 + c) * 32 + og * 8 + j];
            ffma2(acc[0][j], pv0, wv);
            ffma2(acc[1][j], pv1, wv);
            ffma2(acc[2][j], pv2, wv);
            ffma2(acc[3][j], pv3, wv);
        }
        if ((c & 3) == og) {
            *(float4*)&out[((size_t)b * 128 + 64 + c) * N_ + n0] = v;
            float wr = sWr2[c];
            rsum[0] += wr * v.x; rsum[1] += wr * v.y;
            rsum[2] += wr * v.z; rsum[3] += wr * v.w;
        }
    }

    // epilogue: bias + PReLU + store + readout partials
    const float pw = prelu_w[0];
#pragma unroll
    for (int j = 0; j < 8; ++j) {
        int o = og * 16 + 2 * j;
        float b0 = b_out[o], b1 = b_out[o + 1];
        float w0r = W_read[o], w1r = W_read[o + 1];
        float4 r0v, r1v;
#pragma unroll
        for (int n = 0; n < 4; ++n) {
            float2 a = upk2(acc[n][j]);
            float a0 = a.x + b0; a0 = (a0 >= 0.f) ? a0 : pw * a0;
            float a1 = a.y + b1; a1 = (a1 >= 0.f) ? a1 : pw * a1;
            ((float*)&r0v)[n] = a0;
            ((float*)&r1v)[n] = a1;
            rsum[n] += w0r * a0 + w1r * a1;
        }
        *(float4*)&out[((size_t)b * 128 + o) * N_ + n0]     = r0v;
        *(float4*)&out[((size_t)b * 128 + o + 1) * N_ + n0] = r1v;
    }
    // quad-reduce over og and store readout
#pragma unroll
    for (int n = 0; n < 4; ++n) {
        rsum[n] += __shfl_xor_sync(0xFFFFFFFFu, rsum[n], 1);
        rsum[n] += __shfl_xor_sync(0xFFFFFFFFu, rsum[n], 2);
    }
    if (og == 0) {
        float br = b_read[0];
        float4 rv = {rsum[0] + br, rsum[1] + br, rsum[2] + br, rsum[3] + br};
        *(float4*)&rd[(size_t)b * N_ + n0] = rv;
    }
}

extern "C" void kernel_launch(void* const* d_in, const int* in_sizes, int n_in,
                              void* d_out, int out_size) {
    const float* x       = (const float*)d_in[0];
    const float* m       = (const float*)d_in[1];
    const float* u       = (const float*)d_in[2];
    const float* h       = (const float*)d_in[3];
    const float* adj     = (const float*)d_in[4];
    const float* W_in    = (const float*)d_in[5];
    const float* b_in    = (const float*)d_in[6];
    const float* W_gc    = (const float*)d_in[7];
    const float* b_gc    = (const float*)d_in[8];
    const float* W_out   = (const float*)d_in[9];
    const float* b_out   = (const float*)d_in[10];
    const float* W_read  = (const float*)d_in[11];
    const float* b_read  = (const float*)d_in[12];
    const float* prelu_w = (const float*)d_in[13];

    float* read_out = (float*)d_out;
    float* out_big  = (float*)d_out + READ_ELEMS;

    k0_combine<<<68, 128>>>(W_gc, W_in, b_in);
    k_adjf<<<1024, 256>>>(adj);
    k1_yin<<<dim3(N_ / 128, B_), 256>>>(x, m, u, h);
    k2_mma<<<dim3(N_ / 128, (B_ * DMX) / 128), 256>>>(b_gc);
    k34_out<<<dim3(N_ / 256, B_), 256>>>(h, W_out, b_out, prelu_w,
                                         W_read, b_read, out_big, read_out);
}

// round 11
// speedup vs baseline: 3.9398x; 1.0276x over previous
#include <cuda_runtime.h>
#include <cstdint>

// Problem constants
#define B_   128
#define N_   1024
#define DMX  64
#define DIN  68
#define READ_ELEMS (B_ * N_)

// Scratch (device globals; no allocations allowed)
__device__ float    g_C[2 * DMX * DIN];            // combined W_gc_s @ W_in
__device__ float    g_cb[2 * DMX];                 // combined bias
__device__ uint32_t g_Af[2 * 64 * 64 * 128];       // adj A-fragments (bf16)  4 MB
__device__ uint32_t g_Yf[2u * 1024 * 64 * 64];     // Y   B-fragments (bf16) 33.5 MB
__device__ float    g_G[(size_t)B_ * DMX * N_];    // gc result 32 MB

// ================= f32x2 packed-FMA helpers =================
__device__ __forceinline__ unsigned long long pk2(float v) {
    unsigned long long r;
    asm("mov.b64 %0, {%1, %1};" : "=l"(r) : "f"(v));
    return r;
}
__device__ __forceinline__ unsigned long long pkpair(float lo, float hi) {
    unsigned long long r;
    asm("mov.b64 %0, {%1, %2};" : "=l"(r) : "f"(lo), "f"(hi));
    return r;
}
__device__ __forceinline__ void ffma2(unsigned long long& d,
                                      unsigned long long a,
                                      unsigned long long b) {
    asm("fma.rn.f32x2 %0, %1, %2, %0;" : "+l"(d) : "l"(a), "l"(b));
}
__device__ __forceinline__ float2 upk2(unsigned long long v) {
    float2 r;
    asm("mov.b64 {%0, %1}, %2;" : "=f"(r.x), "=f"(r.y) : "l"(v));
    return r;
}

// ================= bf16 helpers =================
__device__ __forceinline__ uint32_t pack_bf16x2(float lo, float hi) {
    uint32_t r;
    asm("cvt.rn.bf16x2.f32 %0, %1, %2;" : "=r"(r) : "f"(hi), "f"(lo));
    return r;
}
__device__ __forceinline__ void mma_bf16(float* c, const uint32_t* a, const uint32_t* b) {
    asm volatile(
        "mma.sync.aligned.m16n8k16.row.col.f32.bf16.bf16.f32 "
        "{%0,%1,%2,%3}, {%4,%5,%6,%7}, {%8,%9}, {%0,%1,%2,%3};"
        : "+f"(c[0]), "+f"(c[1]), "+f"(c[2]), "+f"(c[3])
        : "r"(a[0]), "r"(a[1]), "r"(a[2]), "r"(a[3]),
          "r"(b[0]), "r"(b[1]));
}

// ================= K0: fold W_gc into W_in =================
__global__ void k0_combine(const float* __restrict__ W_gc,
                           const float* __restrict__ W_in,
                           const float* __restrict__ b_in) {
    int d = blockIdx.x;          // 0..67
    int t = threadIdx.x;         // 0..127 -> (s,o)
    int s = t >> 6, o = t & 63;
    const float* wg = W_gc + o * 128 + s * 64;
    float acc = 0.f;
#pragma unroll 8
    for (int c = 0; c < 64; ++c) acc += wg[c] * W_in[c * DIN + d];
    g_C[t * DIN + d] = acc;
    if (d == 0) {
        float ab = 0.f;
        for (int c = 0; c < 64; ++c) ab += wg[c] * b_in[c];
        g_cb[t] = ab;
    }
}

// ================= k_adjf: repack adj into m16k16 A-fragments =================
__global__ void k_adjf(const float* __restrict__ adj) {
    int wg   = blockIdx.x * 8 + (threadIdx.x >> 5);   // 0..8191
    int lane = threadIdx.x & 31;
    int s  = wg >> 12;
    int mf = (wg >> 6) & 63;
    int kc = wg & 63;
    int g = lane >> 2, p = lane & 3;
    const float* rp = adj + ((size_t)(s * N_ + mf * 16 + g)) * N_ + kc * 16 + 2 * p;
    float2 v00 = *(const float2*)rp;
    float2 v10 = *(const float2*)(rp + 8 * N_);
    float2 v01 = *(const float2*)(rp + 8);
    float2 v11 = *(const float2*)(rp + 8 * N_ + 8);
    uint4 o;
    o.x = pack_bf16x2(v00.x, v00.y);
    o.y = pack_bf16x2(v10.x, v10.y);
    o.z = pack_bf16x2(v01.x, v01.y);
    o.w = pack_bf16x2(v11.x, v11.y);
    *(uint4*)&g_Af[(size_t)wg * 128 + lane * 4] = o;
}

// ================= K1: Y = bf16(C @ cat(x,m,u,h) + cb) -> B-frags (smem-coalesced) ===========
// B-frag (s, nf, kc): lane l (n_in=l>>2, p=l&3) holds
//   b0 = (row nf*8+n_in, k 2p..2p+1),  b1 = (same row, k 2p+8..2p+9)
#define STG_STRIDE 66   // padded fragment stride (u32): conflict-free scatter; even -> uint2-aligned
__global__ void __launch_bounds__(256) k1_yin(const float* __restrict__ x,
                                              const float* __restrict__ m,
                                              const float* __restrict__ u,
                                              const float* __restrict__ h) {
    __shared__ __align__(16) char pool[2 * 34 * 136 * 4];   // 36,992 B
    float (*sA)[136] = (float (*)[136])pool;
    float (*sB)[136] = (float (*)[136])(pool + 34 * 136 * 4);
    const int b  = blockIdx.y;
    const int v0 = blockIdx.x * 128;
    const int t  = threadIdx.x;
    const int ty = t >> 4, tx = t & 15;
    const int m0 = ty * 8, n0 = tx * 8;

    unsigned long long acc2[8][4];
#pragma unroll
    for (int i = 0; i < 8; ++i)
#pragma unroll
        for (int j = 0; j < 4; ++j) acc2[i][j] = 0ull;

    for (int kc = 0; kc < 2; ++kc) {
        const int d0 = kc * 34;
        for (int e = t; e < 34 * 128; e += 256) {
            int dd = e >> 7, so = e & 127;
            sA[dd][so] = g_C[so * DIN + d0 + dd];
        }
        for (int e = t; e < 34 * 128; e += 256) {
            int dd = e >> 7, vv = e & 127;
            int d = d0 + dd, v = v0 + vv;
            float val;
            if (d == 0)      val = x[b * N_ + v];
            else if (d == 1) val = m[b * N_ + v];
            else if (d < 4)  val = u[(b * 2 + (d - 2)) * N_ + v];
            else             val = h[((size_t)b * 64 + (d - 4)) * N_ + v];
            sB[dd][vv] = val;
        }
        __syncthreads();
#pragma unroll
        for (int dd = 0; dd < 34; ++dd) {
            float4 a0 = *(const float4*)&sA[dd][m0];
            float4 a1 = *(const float4*)&sA[dd][m0 + 4];
            ulonglong2 bq0 = *(const ulonglong2*)&sB[dd][n0];
            ulonglong2 bq1 = *(const ulonglong2*)&sB[dd][n0 + 4];
            unsigned long long av[8] = {pk2(a0.x), pk2(a0.y), pk2(a0.z), pk2(a0.w),
                                        pk2(a1.x), pk2(a1.y), pk2(a1.z), pk2(a1.w)};
            unsigned long long bv[4] = {bq0.x, bq0.y, bq1.x, bq1.y};
#pragma unroll
            for (int i = 0; i < 8; ++i)
#pragma unroll
                for (int j = 0; j < 4; ++j) ffma2(acc2[i][j], av[i], bv[j]);
        }
        __syncthreads();
    }

    // Scatter into smem staging (fragment layout, padded stride 66 -> conflict-free).
    // Block produces 128 complete fragments: frag = s*64 + nfl*8 + kcl.
    uint32_t* stg = (uint32_t*)pool;
#pragma unroll
    for (int i = 0; i < 8; ++i) {
        int so = m0 + i;
        int s = so >> 6, o = so & 63;
        int nfl = o >> 3, n_in = o & 7;
        float bias = g_cb[so];
#pragma unroll
        for (int j = 0; j < 4; ++j) {
            float2 pr = upk2(acc2[i][j]);
            uint32_t val = pack_bf16x2(pr.x + bias, pr.y + bias);
            int idx = tx * 4 + j;            // local k-pair 0..63
            int kcl = idx >> 3, pp = idx & 7;
            int reg = pp >> 2, p = pp & 3;
            stg[(s * 64 + nfl * 8 + kcl) * STG_STRIDE + (n_in * 4 + p) * 2 + reg] = val;
        }
    }
    __syncthreads();

    // Coalesced copy smem -> gmem as uint2 (stride 66 is even -> 8B-aligned).
    // One warp per fragment: 32 lanes x 8B = 256 contiguous gmem bytes.
    const int kc0 = v0 >> 4;
    for (int e = t; e < 4096; e += 256) {
        int frag = e >> 5, q = e & 31;
        uint2 v = *(const uint2*)&stg[frag * STG_STRIDE + q * 2];
        int s = frag >> 6, rem = frag & 63;
        int nfl = rem >> 3, kcl = rem & 7;
        uint32_t* dst = &g_Yf[((size_t)(s * 1024 + b * 8 + nfl)) * 4096
                              + (kc0 + kcl) * 64 + q * 2];
        *(uint2*)dst = v;
    }
}

// ================= K2: fragment-direct bf16 MMA GEMM (no smem staging) =================
__global__ void __launch_bounds__(256, 2) k2_mma(const float* __restrict__ b_gc) {
    __shared__ float sT[128 * 68];
    const int t = threadIdx.x, lane = t & 31, wid = t >> 5;
    const int wm = wid >> 2, wn = wid & 3;
    const int w0 = blockIdx.x * 128;
    const int r0 = blockIdx.y * 128;

    const uint32_t* aBase = g_Af + (size_t)((w0 >> 4) + wm * 4) * (64 * 128) + lane * 4;
    const uint32_t* bBase = g_Yf + (size_t)((r0 >> 3) + wn * 4) * (64 * 64) + lane * 2;

    float acc[4][4][4];
#pragma unroll
    for (int i = 0; i < 4; ++i)
#pragma unroll
        for (int j = 0; j < 4; ++j)
#pragma unroll
            for (int c = 0; c < 4; ++c) acc[i][j][c] = 0.f;

    uint4 Ab[2][4];
    uint2 Bb[2][4];
#pragma unroll
    for (int i = 0; i < 4; ++i) Ab[0][i] = *(const uint4*)(aBase + i * 8192);
#pragma unroll
    for (int j = 0; j < 4; ++j) Bb[0][j] = *(const uint2*)(bBase + j * 4096);

    for (int kc = 0; kc < 128; ++kc) {
        const int cur = kc & 1;
        if (kc < 127) {
            const int kn = kc + 1;
            const uint32_t* ap = aBase + (kn >> 6) * (64 * 64 * 128) + (kn & 63) * 128;
            const uint32_t* bp = bBase + (kn >> 6) * (1024 * 64 * 64) + (kn & 63) * 64;
#pragma unroll
            for (int i = 0; i < 4; ++i) Ab[cur ^ 1][i] = *(const uint4*)(ap + i * 8192);
#pragma unroll
            for (int j = 0; j < 4; ++j) Bb[cur ^ 1][j] = *(const uint2*)(bp + j * 4096);
        }
#pragma unroll
        for (int i = 0; i < 4; ++i)
#pragma unroll
            for (int j = 0; j < 4; ++j)
                mma_bf16(acc[i][j], (const uint32_t*)&Ab[cur][i],
                         (const uint32_t*)&Bb[cur][j]);
    }

    // Epilogue: transpose through smem, add bias, store coalesced
    const int g = lane >> 2, tq = lane & 3;
    for (int p = 0; p < 2; ++p) {
        __syncthreads();
        if (wm == p) {
#pragma unroll
            for (int i = 0; i < 4; ++i) {
                int wl = i * 16 + g;
#pragma unroll
                for (int j = 0; j < 4; ++j) {
                    int rl = wn * 32 + j * 8 + 2 * tq;
                    sT[rl * 68 + wl]           = acc[i][j][0];
                    sT[(rl + 1) * 68 + wl]     = acc[i][j][1];
                    sT[rl * 68 + wl + 8]       = acc[i][j][2];
                    sT[(rl + 1) * 68 + wl + 8] = acc[i][j][3];
                }
            }
        }
        __syncthreads();
        for (int e = t; e < 128 * 16; e += 256) {
            int rl = e >> 4, c4 = (e & 15) * 4;
            float4 v = *(const float4*)&sT[rl * 68 + c4];
            float bias = b_gc[(r0 + rl) & 63];
            v.x += bias; v.y += bias; v.z += bias; v.w += bias;
            *(float4*)&g_G[(size_t)(r0 + rl) * N_ + w0 + p * 64 + c4] = v;
        }
    }
}

// ================= K34: register-resident out-conv + PReLU + h-copy + readout =================
__global__ void __launch_bounds__(256) k34_out(const float* __restrict__ h,
                                               const float* __restrict__ W_out,
                                               const float* __restrict__ b_out,
                                               const float* __restrict__ prelu_w,
                                               const float* __restrict__ W_read,
                                               const float* __restrict__ b_read,
                                               float* __restrict__ out,
                                               float* __restrict__ rd) {
    __shared__ unsigned long long sW[128 * 32];   // [k][o-pair]
    __shared__ float sWr2[64];                    // W_read[64..127]
    const int b  = blockIdx.y;
    const int nb = blockIdx.x * 256;
    const int t  = threadIdx.x;
    const int og = t & 3;
    const int n0 = nb + (t >> 2) * 4;

    for (int e = t; e < 4096; e += 256) {
        int k = e >> 5, op = e & 31;
        float lo = W_out[(2 * op) * 128 + k];
        float hi = W_out[(2 * op + 1) * 128 + k];
        sW[k * 32 + op] = pkpair(lo, hi);
    }
    if (t < 64) sWr2[t] = W_read[64 + t];
    __syncthreads();

    unsigned long long acc[4][8];
#pragma unroll
    for (int n = 0; n < 4; ++n)
#pragma unroll
        for (int j = 0; j < 8; ++j) acc[n][j] = 0ull;
    float rsum[4] = {0.f, 0.f, 0.f, 0.f};

#pragma unroll 4
    for (int k = 0; k < 64; ++k) {
        float4 v = *(const float4*)&g_G[((size_t)b * 64 + k) * N_ + n0];
        unsigned long long pv0 = pk2(v.x), pv1 = pk2(v.y), pv2 = pk2(v.z), pv3 = pk2(v.w);
#pragma unroll
        for (int j = 0; j < 8; ++j) {
            unsigned long long wv = sW[k * 32 + og * 8 + j];
            ffma2(acc[0][j], pv0, wv);
            ffma2(acc[1][j], pv1, wv);
            ffma2(acc[2][j], pv2, wv);
            ffma2(acc[3][j], pv3, wv);
        }
    }
#pragma unroll 4
    for (int c = 0; c < 64; ++c) {
        float4 v = *(const float4*)&h[((size_t)b * 64 + c) * N_ + n0];
        unsigned long long pv0 = pk2(v.x), pv1 = pk2(v.y), pv2 = pk2(v.z), pv3 = pk2(v.w);
#pragma unroll
        for (int j = 0; j < 8; ++j) {
            unsigned long long wv = sW[(64 + c) * 32 + og * 8 + j];
            ffma2(acc[0][j], pv0, wv);
            ffma2(acc[1][j], pv1, wv);
            ffma2(acc[2][j], pv2, wv);
            ffma2(acc[3][j], pv3, wv);
        }
        if ((c & 3) == og) {
            *(float4*)&out[((size_t)b * 128 + 64 + c) * N_ + n0] = v;
            float wr = sWr2[c];
            rsum[0] += wr * v.x; rsum[1] += wr * v.y;
            rsum[2] += wr * v.z; rsum[3] += wr * v.w;
        }
    }

    const float pw = prelu_w[0];
#pragma unroll
    for (int j = 0; j < 8; ++j) {
        int o = og * 16 + 2 * j;
        float b0 = b_out[o], b1 = b_out[o + 1];
        float w0r = W_read[o], w1r = W_read[o + 1];
        float4 r0v, r1v;
#pragma unroll
        for (int n = 0; n < 4; ++n) {
            float2 a = upk2(acc[n][j]);
            float a0 = a.x + b0; a0 = (a0 >= 0.f) ? a0 : pw * a0;
            float a1 = a.y + b1; a1 = (a1 >= 0.f) ? a1 : pw * a1;
            ((float*)&r0v)[n] = a0;
            ((float*)&r1v)[n] = a1;
            rsum[n] += w0r * a0 + w1r * a1;
        }
        *(float4*)&out[((size_t)b * 128 + o) * N_ + n0]     = r0v;
        *(float4*)&out[((size_t)b * 128 + o + 1) * N_ + n0] = r1v;
    }
#pragma unroll
    for (int n = 0; n < 4; ++n) {
        rsum[n] += __shfl_xor_sync(0xFFFFFFFFu, rsum[n], 1);
        rsum[n] += __shfl_xor_sync(0xFFFFFFFFu, rsum[n], 2);
    }
    if (og == 0) {
        float br = b_read[0];
        float4 rv = {rsum[0] + br, rsum[1] + br, rsum[2] + br, rsum[3] + br};
        *(float4*)&rd[(size_t)b * N_ + n0] = rv;
    }
}

extern "C" void kernel_launch(void* const* d_in, const int* in_sizes, int n_in,
                              void* d_out, int out_size) {
    const float* x       = (const float*)d_in[0];
    const float* m       = (const float*)d_in[1];
    const float* u       = (const float*)d_in[2];
    const float* h       = (const float*)d_in[3];
    const float* adj     = (const float*)d_in[4];
    const float* W_in    = (const float*)d_in[5];
    const float* b_in    = (const float*)d_in[6];
    const float* W_gc    = (const float*)d_in[7];
    const float* b_gc    = (const float*)d_in[8];
    const float* W_out   = (const float*)d_in[9];
    const float* b_out   = (const float*)d_in[10];
    const float* W_read  = (const float*)d_in[11];
    const float* b_read  = (const float*)d_in[12];
    const float* prelu_w = (const float*)d_in[13];

    float* read_out = (float*)d_out;
    float* out_big  = (float*)d_out + READ_ELEMS;

    k0_combine<<<68, 128>>>(W_gc, W_in, b_in);
    k_adjf<<<1024, 256>>>(adj);
    k1_yin<<<dim3(N_ / 128, B_), 256>>>(x, m, u, h);
    k2_mma<<<dim3(N_ / 128, (B_ * DMX) / 128), 256>>>(b_gc);
    k34_out<<<dim3(N_ / 256, B_), 256>>>(h, W_out, b_out, prelu_w,
                                         W_read, b_read, out_big, read_out);
}

// round 12
// speedup vs baseline: 4.1305x; 1.0484x over previous
#include <cuda_runtime.h>
#include <cstdint>

// Problem constants
#define B_   128
#define N_   1024
#define DMX  64
#define DIN  68
#define READ_ELEMS (B_ * N_)

// Scratch (device globals; no allocations allowed)
__device__ float    g_C[2 * DMX * DIN];            // combined W_gc_s @ W_in
__device__ float    g_cb[2 * DMX];                 // combined bias
__device__ uint32_t g_Af[2 * 64 * 64 * 128];       // adj A-fragments (bf16)  4 MB
__device__ uint32_t g_Yf[2u * 1024 * 64 * 64];     // Y   B-fragments (bf16) 33.5 MB

// ================= f32x2 packed-FMA helpers =================
__device__ __forceinline__ unsigned long long pk2(float v) {
    unsigned long long r;
    asm("mov.b64 %0, {%1, %1};" : "=l"(r) : "f"(v));
    return r;
}
__device__ __forceinline__ void ffma2(unsigned long long& d,
                                      unsigned long long a,
                                      unsigned long long b) {
    asm("fma.rn.f32x2 %0, %1, %2, %0;" : "+l"(d) : "l"(a), "l"(b));
}
__device__ __forceinline__ float2 upk2(unsigned long long v) {
    float2 r;
    asm("mov.b64 {%0, %1}, %2;" : "=f"(r.x), "=f"(r.y) : "l"(v));
    return r;
}
union F4U { float4 f; unsigned long long u[2]; };

// ================= bf16 helpers =================
__device__ __forceinline__ uint32_t pack_bf16x2(float lo, float hi) {
    uint32_t r;
    asm("cvt.rn.bf16x2.f32 %0, %1, %2;" : "=r"(r) : "f"(hi), "f"(lo));
    return r;
}
__device__ __forceinline__ void mma_bf16(float* c, const uint32_t* a, const uint32_t* b) {
    asm volatile(
        "mma.sync.aligned.m16n8k16.row.col.f32.bf16.bf16.f32 "
        "{%0,%1,%2,%3}, {%4,%5,%6,%7}, {%8,%9}, {%0,%1,%2,%3};"
        : "+f"(c[0]), "+f"(c[1]), "+f"(c[2]), "+f"(c[3])
        : "r"(a[0]), "r"(a[1]), "r"(a[2]), "r"(a[3]),
          "r"(b[0]), "r"(b[1]));
}

// ================= K0: fold W_gc into W_in =================
__global__ void k0_combine(const float* __restrict__ W_gc,
                           const float* __restrict__ W_in,
                           const float* __restrict__ b_in) {
    int d = blockIdx.x;          // 0..67
    int t = threadIdx.x;         // 0..127 -> (s,o)
    int s = t >> 6, o = t & 63;
    const float* wg = W_gc + o * 128 + s * 64;
    float acc = 0.f;
#pragma unroll 8
    for (int c = 0; c < 64; ++c) acc += wg[c] * W_in[c * DIN + d];
    g_C[t * DIN + d] = acc;
    if (d == 0) {
        float ab = 0.f;
        for (int c = 0; c < 64; ++c) ab += wg[c] * b_in[c];
        g_cb[t] = ab;
    }
}

// ================= k_adjf: repack adj into m16k16 A-fragments =================
__global__ void k_adjf(const float* __restrict__ adj) {
    int wg   = blockIdx.x * 8 + (threadIdx.x >> 5);   // 0..8191
    int lane = threadIdx.x & 31;
    int s  = wg >> 12;
    int mf = (wg >> 6) & 63;
    int kc = wg & 63;
    int g = lane >> 2, p = lane & 3;
    const float* rp = adj + ((size_t)(s * N_ + mf * 16 + g)) * N_ + kc * 16 + 2 * p;
    float2 v00 = *(const float2*)rp;
    float2 v10 = *(const float2*)(rp + 8 * N_);
    float2 v01 = *(const float2*)(rp + 8);
    float2 v11 = *(const float2*)(rp + 8 * N_ + 8);
    uint4 o;
    o.x = pack_bf16x2(v00.x, v00.y);
    o.y = pack_bf16x2(v10.x, v10.y);
    o.z = pack_bf16x2(v01.x, v01.y);
    o.w = pack_bf16x2(v11.x, v11.y);
    *(uint4*)&g_Af[(size_t)wg * 128 + lane * 4] = o;
}

// ================= K1: Y = bf16(C @ cat(x,m,u,h) + cb) -> B-frags (smem-coalesced) ===========
#define STG_STRIDE 66   // padded fragment stride (u32): conflict-free scatter; even -> uint2-aligned
__global__ void __launch_bounds__(256) k1_yin(const float* __restrict__ x,
                                              const float* __restrict__ m,
                                              const float* __restrict__ u,
                                              const float* __restrict__ h) {
    __shared__ __align__(16) char pool[2 * 34 * 136 * 4];   // 36,992 B
    float (*sA)[136] = (float (*)[136])pool;
    float (*sB)[136] = (float (*)[136])(pool + 34 * 136 * 4);
    const int b  = blockIdx.y;
    const int v0 = blockIdx.x * 128;
    const int t  = threadIdx.x;
    const int ty = t >> 4, tx = t & 15;
    const int m0 = ty * 8, n0 = tx * 8;

    unsigned long long acc2[8][4];
#pragma unroll
    for (int i = 0; i < 8; ++i)
#pragma unroll
        for (int j = 0; j < 4; ++j) acc2[i][j] = 0ull;

    for (int kc = 0; kc < 2; ++kc) {
        const int d0 = kc * 34;
        for (int e = t; e < 34 * 128; e += 256) {
            int dd = e >> 7, so = e & 127;
            sA[dd][so] = g_C[so * DIN + d0 + dd];
        }
        for (int e = t; e < 34 * 128; e += 256) {
            int dd = e >> 7, vv = e & 127;
            int d = d0 + dd, v = v0 + vv;
            float val;
            if (d == 0)      val = x[b * N_ + v];
            else if (d == 1) val = m[b * N_ + v];
            else if (d < 4)  val = u[(b * 2 + (d - 2)) * N_ + v];
            else             val = h[((size_t)b * 64 + (d - 4)) * N_ + v];
            sB[dd][vv] = val;
        }
        __syncthreads();
#pragma unroll
        for (int dd = 0; dd < 34; ++dd) {
            float4 a0 = *(const float4*)&sA[dd][m0];
            float4 a1 = *(const float4*)&sA[dd][m0 + 4];
            ulonglong2 bq0 = *(const ulonglong2*)&sB[dd][n0];
            ulonglong2 bq1 = *(const ulonglong2*)&sB[dd][n0 + 4];
            unsigned long long av[8] = {pk2(a0.x), pk2(a0.y), pk2(a0.z), pk2(a0.w),
                                        pk2(a1.x), pk2(a1.y), pk2(a1.z), pk2(a1.w)};
            unsigned long long bv[4] = {bq0.x, bq0.y, bq1.x, bq1.y};
#pragma unroll
            for (int i = 0; i < 8; ++i)
#pragma unroll
                for (int j = 0; j < 4; ++j) ffma2(acc2[i][j], av[i], bv[j]);
        }
        __syncthreads();
    }

    // Scatter into smem staging (fragment layout, padded stride 66 -> conflict-free).
    uint32_t* stg = (uint32_t*)pool;
#pragma unroll
    for (int i = 0; i < 8; ++i) {
        int so = m0 + i;
        int s = so >> 6, o = so & 63;
        int nfl = o >> 3, n_in = o & 7;
        float bias = g_cb[so];
#pragma unroll
        for (int j = 0; j < 4; ++j) {
            float2 pr = upk2(acc2[i][j]);
            uint32_t val = pack_bf16x2(pr.x + bias, pr.y + bias);
            int idx = tx * 4 + j;            // local k-pair 0..63
            int kcl = idx >> 3, pp = idx & 7;
            int reg = pp >> 2, p = pp & 3;
            stg[(s * 64 + nfl * 8 + kcl) * STG_STRIDE + (n_in * 4 + p) * 2 + reg] = val;
        }
    }
    __syncthreads();

    // Coalesced copy smem -> gmem as uint2 (stride 66 even -> 8B-aligned).
    const int kc0 = v0 >> 4;
    for (int e = t; e < 4096; e += 256) {
        int frag = e >> 5, q = e & 31;
        uint2 v = *(const uint2*)&stg[frag * STG_STRIDE + q * 2];
        int s = frag >> 6, rem = frag & 63;
        int nfl = rem >> 3, kcl = rem & 7;
        uint32_t* dst = &g_Yf[((size_t)(s * 1024 + b * 8 + nfl)) * 4096
                              + (kc0 + kcl) * 64 + q * 2];
        *(uint2*)dst = v;
    }
}

// ================= K2F: fragment-direct bf16 MMA + FUSED out-conv/PReLU/h-copy/readout ========
// Dynamic smem layout (floats):
//   sTF  [128 ch][132]      0     .. 16896   (67,584 B)
//   sWoF [128 c ][68 o]     16896 .. 25600   (34,816 B)
//   sWr  [128]              25600 .. 25728
//   sBo  [64]               25728 .. 25792
#define K2F_SMEM_BYTES (25792 * 4)

__global__ void __launch_bounds__(256, 2) k2_fused(
    const float* __restrict__ h, const float* __restrict__ b_gc,
    const float* __restrict__ W_out, const float* __restrict__ b_out,
    const float* __restrict__ prelu_w, const float* __restrict__ W_read,
    const float* __restrict__ b_read,
    float* __restrict__ out, float* __restrict__ rd) {
    extern __shared__ __align__(16) float SMF[];
    float* sTF  = SMF;
    float* sWoF = SMF + 16896;
    float* sWr  = SMF + 25600;
    float* sBo  = SMF + 25728;

    const int t = threadIdx.x, lane = t & 31, wid = t >> 5;
    const int wm = wid >> 2, wn = wid & 3;
    const int w0 = blockIdx.x * 128;
    const int r0 = blockIdx.y * 128;
    const int b0 = blockIdx.y * 2;

    // One-time weight staging (coalesced gmem reads)
    for (int e = t; e < 8192; e += 256) {
        int c = e & 127, o = e >> 7;
        sWoF[c * 68 + o] = W_out[o * 128 + c];
    }
    if (t < 128) sWr[t] = W_read[t];
    if (t < 64)  sBo[t] = b_out[t];

    // ---- MMA mainloop (identical to prior k2_mma) ----
    const uint32_t* aBase = g_Af + (size_t)((w0 >> 4) + wm * 4) * (64 * 128) + lane * 4;
    const uint32_t* bBase = g_Yf + (size_t)((r0 >> 3) + wn * 4) * (64 * 64) + lane * 2;

    float acc[4][4][4];
#pragma unroll
    for (int i = 0; i < 4; ++i)
#pragma unroll
        for (int j = 0; j < 4; ++j)
#pragma unroll
            for (int c = 0; c < 4; ++c) acc[i][j][c] = 0.f;

    uint4 Ab[2][4];
    uint2 Bb[2][4];
#pragma unroll
    for (int i = 0; i < 4; ++i) Ab[0][i] = *(const uint4*)(aBase + i * 8192);
#pragma unroll
    for (int j = 0; j < 4; ++j) Bb[0][j] = *(const uint2*)(bBase + j * 4096);

    for (int kc = 0; kc < 128; ++kc) {
        const int cur = kc & 1;
        if (kc < 127) {
            const int kn = kc + 1;
            const uint32_t* ap = aBase + (kn >> 6) * (64 * 64 * 128) + (kn & 63) * 128;
            const uint32_t* bp = bBase + (kn >> 6) * (1024 * 64 * 64) + (kn & 63) * 64;
#pragma unroll
            for (int i = 0; i < 4; ++i) Ab[cur ^ 1][i] = *(const uint4*)(ap + i * 8192);
#pragma unroll
            for (int j = 0; j < 4; ++j) Bb[cur ^ 1][j] = *(const uint2*)(bp + j * 4096);
        }
#pragma unroll
        for (int i = 0; i < 4; ++i)
#pragma unroll
            for (int j = 0; j < 4; ++j)
                mma_bf16(acc[i][j], (const uint32_t*)&Ab[cur][i],
                         (const uint32_t*)&Bb[cur][j]);
    }

    // ---- Transpose accumulators (+ b_gc bias) into full sTF tile ----
    const int g = lane >> 2, tq = lane & 3;
#pragma unroll
    for (int i = 0; i < 4; ++i) {
        int wl = wm * 64 + i * 16 + g;
#pragma unroll
        for (int j = 0; j < 4; ++j) {
            int rl = wn * 32 + j * 8 + 2 * tq;
            float bias0 = b_gc[rl & 63];
            float bias1 = b_gc[(rl + 1) & 63];
            sTF[rl * 132 + wl]            = acc[i][j][0] + bias0;
            sTF[(rl + 1) * 132 + wl]      = acc[i][j][1] + bias1;
            sTF[rl * 132 + wl + 8]        = acc[i][j][2] + bias0;
            sTF[(rl + 1) * 132 + wl + 8]  = acc[i][j][3] + bias1;
        }
    }
    __syncthreads();

    // ---- Fused epilogue: out-conv + PReLU + h-copy + readout ----
    const int og = t & 15;            // o-group: o = og*4..+3, h-channels og*4..+3
    const int nq = t >> 4;            // node quad within 64-node half
    const float pw = prelu_w[0];
    const float brd = b_read[0];

    for (int p = 0; p < 2; ++p) {
        const int node = w0 + p * 64 + nq * 4;
        const float* col = sTF + p * 64 + nq * 4;
        const float* hb0 = h + (size_t)(b0 * 64) * N_ + node;
        const float* hb1 = hb0 + (size_t)64 * N_;

        unsigned long long ac[2][4][2];
#pragma unroll
        for (int bb = 0; bb < 2; ++bb)
#pragma unroll
            for (int i = 0; i < 4; ++i) { ac[bb][i][0] = 0ull; ac[bb][i][1] = 0ull; }

        // gc channels (from smem tile)
#pragma unroll 4
        for (int c = 0; c < 64; ++c) {
            F4U v0; v0.f = *(const float4*)(col + c * 132);
            F4U v1; v1.f = *(const float4*)(col + (64 + c) * 132);
            float4 wq = *(const float4*)&sWoF[c * 68 + og * 4];
            const float* wf = (const float*)&wq;
#pragma unroll
            for (int i = 0; i < 4; ++i) {
                unsigned long long wp = pk2(wf[i]);
                ffma2(ac[0][i][0], wp, v0.u[0]);
                ffma2(ac[0][i][1], wp, v0.u[1]);
                ffma2(ac[1][i][0], wp, v1.u[0]);
                ffma2(ac[1][i][1], wp, v1.u[1]);
            }
        }
        // h channels (from gmem)
#pragma unroll 4
        for (int c = 0; c < 64; ++c) {
            F4U h0; h0.f = *(const float4*)(hb0 + (size_t)c * N_);
            F4U h1; h1.f = *(const float4*)(hb1 + (size_t)c * N_);
            float4 wq = *(const float4*)&sWoF[(64 + c) * 68 + og * 4];
            const float* wf = (const float*)&wq;
#pragma unroll
            for (int i = 0; i < 4; ++i) {
                unsigned long long wp = pk2(wf[i]);
                ffma2(ac[0][i][0], wp, h0.u[0]);
                ffma2(ac[0][i][1], wp, h0.u[1]);
                ffma2(ac[1][i][0], wp, h1.u[0]);
                ffma2(ac[1][i][1], wp, h1.u[1]);
            }
        }

        // h-copy (4 channels per og-group) + h readout partials
        unsigned long long rsp[2][2] = {0ull, 0ull, 0ull, 0ull};
#pragma unroll
        for (int cl = 0; cl < 4; ++cl) {
            int c = og * 4 + cl;
            F4U h0; h0.f = *(const float4*)(hb0 + (size_t)c * N_);
            F4U h1; h1.f = *(const float4*)(hb1 + (size_t)c * N_);
            *(float4*)&out[((size_t)(b0 * 128 + 64 + c)) * N_ + node] = h0.f;
            *(float4*)&out[((size_t)((b0 + 1) * 128 + 64 + c)) * N_ + node] = h1.f;
            unsigned long long wp = pk2(sWr[64 + c]);
            ffma2(rsp[0][0], wp, h0.u[0]);
            ffma2(rsp[0][1], wp, h0.u[1]);
            ffma2(rsp[1][0], wp, h1.u[0]);
            ffma2(rsp[1][1], wp, h1.u[1]);
        }

        // bias + PReLU + store conv outputs + conv readout partials
#pragma unroll
        for (int i = 0; i < 4; ++i) {
            int o = og * 4 + i;
            float bo = sBo[o];
            unsigned long long wrp = pk2(sWr[o]);
#pragma unroll
            for (int bb = 0; bb < 2; ++bb) {
                float2 a0 = upk2(ac[bb][i][0]);
                float2 a1 = upk2(ac[bb][i][1]);
                F4U vv;
                float x0 = a0.x + bo; x0 = (x0 >= 0.f) ? x0 : pw * x0;
                float x1 = a0.y + bo; x1 = (x1 >= 0.f) ? x1 : pw * x1;
                float x2 = a1.x + bo; x2 = (x2 >= 0.f) ? x2 : pw * x2;
                float x3 = a1.y + bo; x3 = (x3 >= 0.f) ? x3 : pw * x3;
                vv.f.x = x0; vv.f.y = x1; vv.f.z = x2; vv.f.w = x3;
                *(float4*)&out[((size_t)((b0 + bb) * 128 + o)) * N_ + node] = vv.f;
                ffma2(rsp[bb][0], wrp, vv.u[0]);
                ffma2(rsp[bb][1], wrp, vv.u[1]);
            }
        }

        // reduce readout partials across the 16 og-groups (in-warp butterfly)
        float rs[2][4];
#pragma unroll
        for (int bb = 0; bb < 2; ++bb) {
            float2 r0 = upk2(rsp[bb][0]);
            float2 r1 = upk2(rsp[bb][1]);
            rs[bb][0] = r0.x; rs[bb][1] = r0.y; rs[bb][2] = r1.x; rs[bb][3] = r1.y;
        }
#pragma unroll
        for (int mask = 1; mask < 16; mask <<= 1)
#pragma unroll
            for (int bb = 0; bb < 2; ++bb)
#pragma unroll
                for (int k = 0; k < 4; ++k)
                    rs[bb][k] += __shfl_xor_sync(0xFFFFFFFFu, rs[bb][k], mask);
        if (og == 0) {
#pragma unroll
            for (int bb = 0; bb < 2; ++bb) {
                float4 o4;
                o4.x = rs[bb][0] + brd; o4.y = rs[bb][1] + brd;
                o4.z = rs[bb][2] + brd; o4.w = rs[bb][3] + brd;
                *(float4*)&rd[(size_t)(b0 + bb) * N_ + node] = o4;
            }
        }
    }
}

extern "C" void kernel_launch(void* const* d_in, const int* in_sizes, int n_in,
                              void* d_out, int out_size) {
    const float* x       = (const float*)d_in[0];
    const float* m       = (const float*)d_in[1];
    const float* u       = (const float*)d_in[2];
    const float* h       = (const float*)d_in[3];
    const float* adj     = (const float*)d_in[4];
    const float* W_in    = (const float*)d_in[5];
    const float* b_in    = (const float*)d_in[6];
    const float* W_gc    = (const float*)d_in[7];
    const float* b_gc    = (const float*)d_in[8];
    const float* W_out   = (const float*)d_in[9];
    const float* b_out   = (const float*)d_in[10];
    const float* W_read  = (const float*)d_in[11];
    const float* b_read  = (const float*)d_in[12];
    const float* prelu_w = (const float*)d_in[13];

    float* read_out = (float*)d_out;
    float* out_big  = (float*)d_out + READ_ELEMS;

    static bool attr_set = false;
    if (!attr_set) {
        cudaFuncSetAttribute(k2_fused, cudaFuncAttributeMaxDynamicSharedMemorySize,
                             K2F_SMEM_BYTES);
        attr_set = true;
    }

    k0_combine<<<68, 128>>>(W_gc, W_in, b_in);
    k_adjf<<<1024, 256>>>(adj);
    k1_yin<<<dim3(N_ / 128, B_), 256>>>(x, m, u, h);
    k2_fused<<<dim3(N_ / 128, (B_ * DMX) / 128), 256, K2F_SMEM_BYTES>>>(
        h, b_gc, W_out, b_out, prelu_w, W_read, b_read, out_big, read_out);
}

// round 13
// speedup vs baseline: 5.0677x; 1.2269x over previous
#include <cuda_runtime.h>
#include <cstdint>

// Problem constants
#define B_   128
#define N_   1024
#define DMX  64
#define DIN  68
#define READ_ELEMS (B_ * N_)

// Scratch (device globals; no allocations allowed)
__device__ float    g_C[2 * DMX * DIN];            // combined W_gc_s @ W_in (fp32)
__device__ float    g_cb[2 * DMX];                 // combined bias
__device__ uint32_t g_Cf[5 * 8 * 128];             // C as bf16 A-fragments (K padded to 80) 20 KB
__device__ uint32_t g_Af[2 * 64 * 64 * 128];       // adj A-fragments (bf16)  4 MB
__device__ uint32_t g_Yf[2u * 1024 * 64 * 64];     // Y   B-fragments (bf16) 33.5 MB

// ================= f32x2 packed-FMA helpers =================
__device__ __forceinline__ unsigned long long pk2(float v) {
    unsigned long long r;
    asm("mov.b64 %0, {%1, %1};" : "=l"(r) : "f"(v));
    return r;
}
__device__ __forceinline__ void ffma2(unsigned long long& d,
                                      unsigned long long a,
                                      unsigned long long b) {
    asm("fma.rn.f32x2 %0, %1, %2, %0;" : "+l"(d) : "l"(a), "l"(b));
}
__device__ __forceinline__ float2 upk2(unsigned long long v) {
    float2 r;
    asm("mov.b64 {%0, %1}, %2;" : "=f"(r.x), "=f"(r.y) : "l"(v));
    return r;
}
union F4U { float4 f; unsigned long long u[2]; };

// ================= bf16 helpers =================
__device__ __forceinline__ uint32_t pack_bf16x2(float lo, float hi) {
    uint32_t r;
    asm("cvt.rn.bf16x2.f32 %0, %1, %2;" : "=r"(r) : "f"(hi), "f"(lo));
    return r;
}
__device__ __forceinline__ void mma_bf16(float* c, const uint32_t* a, const uint32_t* b) {
    asm volatile(
        "mma.sync.aligned.m16n8k16.row.col.f32.bf16.bf16.f32 "
        "{%0,%1,%2,%3}, {%4,%5,%6,%7}, {%8,%9}, {%0,%1,%2,%3};"
        : "+f"(c[0]), "+f"(c[1]), "+f"(c[2]), "+f"(c[3])
        : "r"(a[0]), "r"(a[1]), "r"(a[2]), "r"(a[3]),
          "r"(b[0]), "r"(b[1]));
}

// ================= K0: fold W_gc into W_in =================
__global__ void k0_combine(const float* __restrict__ W_gc,
                           const float* __restrict__ W_in,
                           const float* __restrict__ b_in) {
    int d = blockIdx.x;          // 0..67
    int t = threadIdx.x;         // 0..127 -> (s,o)
    int s = t >> 6, o = t & 63;
    const float* wg = W_gc + o * 128 + s * 64;
    float acc = 0.f;
#pragma unroll 8
    for (int c = 0; c < 64; ++c) acc += wg[c] * W_in[c * DIN + d];
    g_C[t * DIN + d] = acc;
    if (d == 0) {
        float ab = 0.f;
        for (int c = 0; c < 64; ++c) ab += wg[c] * b_in[c];
        g_cb[t] = ab;
    }
}

// ================= k_cf: pack C into bf16 A-fragments (K padded 68->80) =================
__device__ __forceinline__ float c_rd(int r, int d) {
    return (d < DIN) ? g_C[r * DIN + d] : 0.f;
}
__global__ void k_cf() {
    int wg   = blockIdx.x * 8 + (threadIdx.x >> 5);   // 0..39
    int lane = threadIdx.x & 31;
    int kc = wg >> 3, mf = wg & 7;
    int g = lane >> 2, p = lane & 3;
    int d0 = kc * 16 + 2 * p;
    int r0 = mf * 16 + g, r1 = r0 + 8;
    uint4 o;
    o.x = pack_bf16x2(c_rd(r0, d0),     c_rd(r0, d0 + 1));
    o.y = pack_bf16x2(c_rd(r1, d0),     c_rd(r1, d0 + 1));
    o.z = pack_bf16x2(c_rd(r0, d0 + 8), c_rd(r0, d0 + 9));
    o.w = pack_bf16x2(c_rd(r1, d0 + 8), c_rd(r1, d0 + 9));
    *(uint4*)&g_Cf[(kc * 8 + mf) * 128 + lane * 4] = o;
}

// ================= k_adjf: repack adj into m16k16 A-fragments =================
__global__ void k_adjf(const float* __restrict__ adj) {
    int wg   = blockIdx.x * 8 + (threadIdx.x >> 5);   // 0..8191
    int lane = threadIdx.x & 31;
    int s  = wg >> 12;
    int mf = (wg >> 6) & 63;
    int kc = wg & 63;
    int g = lane >> 2, p = lane & 3;
    const float* rp = adj + ((size_t)(s * N_ + mf * 16 + g)) * N_ + kc * 16 + 2 * p;
    float2 v00 = *(const float2*)rp;
    float2 v10 = *(const float2*)(rp + 8 * N_);
    float2 v01 = *(const float2*)(rp + 8);
    float2 v11 = *(const float2*)(rp + 8 * N_ + 8);
    uint4 o;
    o.x = pack_bf16x2(v00.x, v00.y);
    o.y = pack_bf16x2(v10.x, v10.y);
    o.z = pack_bf16x2(v01.x, v01.y);
    o.w = pack_bf16x2(v11.x, v11.y);
    *(uint4*)&g_Af[(size_t)wg * 128 + lane * 4] = o;
}

// ================= K1: Y = bf16 MMA (C @ cat(x,m,u,h)) + cb -> B-frags direct ==========
// Grid (N/128, B), 256 thr (8 warps). Warp w owns rows so = w*16..+15.
// smem sP[node][dp]: bf16x2 input pairs, node-stride 44 u32 (conflict-free reads).
__global__ void __launch_bounds__(256) k1_yin(const float* __restrict__ x,
                                              const float* __restrict__ m,
                                              const float* __restrict__ u,
                                              const float* __restrict__ h) {
    __shared__ uint32_t sP[128 * 44];
    const int b  = blockIdx.y;
    const int v0 = blockIdx.x * 128;
    const int t  = threadIdx.x;
    const int w  = t >> 5, lane = t & 31;
    const int g  = lane >> 2, p = lane & 3;

    // Stage input pairs (d-sequence: x, m, u0, u1, h0..h63; dp>=34 zero-pad)
    for (int e = t; e < 40 * 128; e += 256) {
        int dp = e >> 7, nd = e & 127;
        int v = v0 + nd;
        float lo, hi;
        if (dp == 0)       { lo = x[b * N_ + v];             hi = m[b * N_ + v]; }
        else if (dp == 1)  { lo = u[(2 * b) * N_ + v];       hi = u[(2 * b + 1) * N_ + v]; }
        else if (dp < 34)  {
            int c = 2 * dp - 4;
            lo = h[((size_t)b * 64 + c) * N_ + v];
            hi = h[((size_t)b * 64 + c + 1) * N_ + v];
        } else             { lo = 0.f; hi = 0.f; }
        sP[nd * 44 + dp] = pack_bf16x2(lo, hi);
    }
    __syncthreads();

    // Preload A-fragments (C weights) for this warp's row range
    uint4 Af[5];
#pragma unroll
    for (int kc = 0; kc < 5; ++kc)
        Af[kc] = *(const uint4*)&g_Cf[(kc * 8 + w) * 128 + lane * 4];

    float acc[16][4];
#pragma unroll
    for (int i = 0; i < 16; ++i)
#pragma unroll
        for (int c = 0; c < 4; ++c) acc[i][c] = 0.f;

#pragma unroll
    for (int kc = 0; kc < 5; ++kc) {
#pragma unroll
        for (int nf8 = 0; nf8 < 16; ++nf8) {
            uint32_t bf[2];
            bf[0] = sP[(nf8 * 8 + g) * 44 + 8 * kc + p];
            bf[1] = sP[(nf8 * 8 + g) * 44 + 8 * kc + p + 4];
            mma_bf16(acc[nf8], (const uint32_t*)&Af[kc], bf);
        }
    }

    // Epilogue: bias + pack + dense uint2 stores into g_Yf fragment layout.
    const int s = w >> 2;
    const float cb0 = g_cb[w * 16 + g];
    const float cb1 = g_cb[w * 16 + 8 + g];
    const int nfl0 = (w & 3) * 2;
    const size_t base0 = ((size_t)(s * 1024 + b * 8 + nfl0)) * 4096;
    const size_t base1 = base0 + 4096;
    const int off = (g * 4 + p) * 2;
    const int kc0 = v0 >> 4;
#pragma unroll
    for (int e = 0; e < 8; ++e) {
        uint2 lo_v, hi_v;
        lo_v.x = pack_bf16x2(acc[2 * e][0] + cb0, acc[2 * e][1] + cb0);
        lo_v.y = pack_bf16x2(acc[2 * e + 1][0] + cb0, acc[2 * e + 1][1] + cb0);
        hi_v.x = pack_bf16x2(acc[2 * e][2] + cb1, acc[2 * e][3] + cb1);
        hi_v.y = pack_bf16x2(acc[2 * e + 1][2] + cb1, acc[2 * e + 1][3] + cb1);
        *(uint2*)&g_Yf[base0 + (size_t)(kc0 + e) * 64 + off] = lo_v;
        *(uint2*)&g_Yf[base1 + (size_t)(kc0 + e) * 64 + off] = hi_v;
    }
}

// ================= K2F: fragment-direct bf16 MMA + FUSED out-conv/PReLU/h-copy/readout ========
// Dynamic smem layout (floats):
//   sTF  [128 ch][132]      0     .. 16896   (67,584 B)
//   sWoF [128 c ][68 o]     16896 .. 25600   (34,816 B)
//   sWr  [128]              25600 .. 25728
//   sBo  [64]               25728 .. 25792
#define K2F_SMEM_BYTES (25792 * 4)

__global__ void __launch_bounds__(256, 2) k2_fused(
    const float* __restrict__ h, const float* __restrict__ b_gc,
    const float* __restrict__ W_out, const float* __restrict__ b_out,
    const float* __restrict__ prelu_w, const float* __restrict__ W_read,
    const float* __restrict__ b_read,
    float* __restrict__ out, float* __restrict__ rd) {
    extern __shared__ __align__(16) float SMF[];
    float* sTF  = SMF;
    float* sWoF = SMF + 16896;
    float* sWr  = SMF + 25600;
    float* sBo  = SMF + 25728;

    const int t = threadIdx.x, lane = t & 31, wid = t >> 5;
    const int wm = wid >> 2, wn = wid & 3;
    const int w0 = blockIdx.x * 128;
    const int r0 = blockIdx.y * 128;
    const int b0 = blockIdx.y * 2;

    // One-time weight staging (coalesced gmem reads)
    for (int e = t; e < 8192; e += 256) {
        int c = e & 127, o = e >> 7;
        sWoF[c * 68 + o] = W_out[o * 128 + c];
    }
    if (t < 128) sWr[t] = W_read[t];
    if (t < 64)  sBo[t] = b_out[t];

    // ---- MMA mainloop ----
    const uint32_t* aBase = g_Af + (size_t)((w0 >> 4) + wm * 4) * (64 * 128) + lane * 4;
    const uint32_t* bBase = g_Yf + (size_t)((r0 >> 3) + wn * 4) * (64 * 64) + lane * 2;

    float acc[4][4][4];
#pragma unroll
    for (int i = 0; i < 4; ++i)
#pragma unroll
        for (int j = 0; j < 4; ++j)
#pragma unroll
            for (int c = 0; c < 4; ++c) acc[i][j][c] = 0.f;

    uint4 Ab[2][4];
    uint2 Bb[2][4];
#pragma unroll
    for (int i = 0; i < 4; ++i) Ab[0][i] = *(const uint4*)(aBase + i * 8192);
#pragma unroll
    for (int j = 0; j < 4; ++j) Bb[0][j] = *(const uint2*)(bBase + j * 4096);

    for (int kc = 0; kc < 128; ++kc) {
        const int cur = kc & 1;
        if (kc < 127) {
            const int kn = kc + 1;
            const uint32_t* ap = aBase + (kn >> 6) * (64 * 64 * 128) + (kn & 63) * 128;
            const uint32_t* bp = bBase + (kn >> 6) * (1024 * 64 * 64) + (kn & 63) * 64;
#pragma unroll
            for (int i = 0; i < 4; ++i) Ab[cur ^ 1][i] = *(const uint4*)(ap + i * 8192);
#pragma unroll
            for (int j = 0; j < 4; ++j) Bb[cur ^ 1][j] = *(const uint2*)(bp + j * 4096);
        }
#pragma unroll
        for (int i = 0; i < 4; ++i)
#pragma unroll
            for (int j = 0; j < 4; ++j)
                mma_bf16(acc[i][j], (const uint32_t*)&Ab[cur][i],
                         (const uint32_t*)&Bb[cur][j]);
    }

    // ---- Transpose accumulators (+ b_gc bias) into full sTF tile ----
    const int g = lane >> 2, tq = lane & 3;
#pragma unroll
    for (int i = 0; i < 4; ++i) {
        int wl = wm * 64 + i * 16 + g;
#pragma unroll
        for (int j = 0; j < 4; ++j) {
            int rl = wn * 32 + j * 8 + 2 * tq;
            float bias0 = b_gc[rl & 63];
            float bias1 = b_gc[(rl + 1) & 63];
            sTF[rl * 132 + wl]            = acc[i][j][0] + bias0;
            sTF[(rl + 1) * 132 + wl]      = acc[i][j][1] + bias1;
            sTF[rl * 132 + wl + 8]        = acc[i][j][2] + bias0;
            sTF[(rl + 1) * 132 + wl + 8]  = acc[i][j][3] + bias1;
        }
    }
    __syncthreads();

    // ---- Fused epilogue: out-conv + PReLU + h-copy + readout ----
    const int og = t & 15;            // o-group: o = og*4..+3, h-channels og*4..+3
    const int nq = t >> 4;            // node quad within 64-node half
    const float pw = prelu_w[0];
    const float brd = b_read[0];

    for (int p = 0; p < 2; ++p) {
        const int node = w0 + p * 64 + nq * 4;
        const float* col = sTF + p * 64 + nq * 4;
        const float* hb0 = h + (size_t)(b0 * 64) * N_ + node;
        const float* hb1 = hb0 + (size_t)64 * N_;

        unsigned long long ac[2][4][2];
#pragma unroll
        for (int bb = 0; bb < 2; ++bb)
#pragma unroll
            for (int i = 0; i < 4; ++i) { ac[bb][i][0] = 0ull; ac[bb][i][1] = 0ull; }

        // gc channels (from smem tile)
#pragma unroll 4
        for (int c = 0; c < 64; ++c) {
            F4U v0; v0.f = *(const float4*)(col + c * 132);
            F4U v1; v1.f = *(const float4*)(col + (64 + c) * 132);
            float4 wq = *(const float4*)&sWoF[c * 68 + og * 4];
            const float* wf = (const float*)&wq;
#pragma unroll
            for (int i = 0; i < 4; ++i) {
                unsigned long long wp = pk2(wf[i]);
                ffma2(ac[0][i][0], wp, v0.u[0]);
                ffma2(ac[0][i][1], wp, v0.u[1]);
                ffma2(ac[1][i][0], wp, v1.u[0]);
                ffma2(ac[1][i][1], wp, v1.u[1]);
            }
        }
        // h channels (from gmem)
#pragma unroll 4
        for (int c = 0; c < 64; ++c) {
            F4U h0; h0.f = *(const float4*)(hb0 + (size_t)c * N_);
            F4U h1; h1.f = *(const float4*)(hb1 + (size_t)c * N_);
            float4 wq = *(const float4*)&sWoF[(64 + c) * 68 + og * 4];
            const float* wf = (const float*)&wq;
#pragma unroll
            for (int i = 0; i < 4; ++i) {
                unsigned long long wp = pk2(wf[i]);
                ffma2(ac[0][i][0], wp, h0.u[0]);
                ffma2(ac[0][i][1], wp, h0.u[1]);
                ffma2(ac[1][i][0], wp, h1.u[0]);
                ffma2(ac[1][i][1], wp, h1.u[1]);
            }
        }

        // h-copy (4 channels per og-group) + h readout partials
        unsigned long long rsp[2][2] = {0ull, 0ull, 0ull, 0ull};
#pragma unroll
        for (int cl = 0; cl < 4; ++cl) {
            int c = og * 4 + cl;
            F4U h0; h0.f = *(const float4*)(hb0 + (size_t)c * N_);
            F4U h1; h1.f = *(const float4*)(hb1 + (size_t)c * N_);
            *(float4*)&out[((size_t)(b0 * 128 + 64 + c)) * N_ + node] = h0.f;
            *(float4*)&out[((size_t)((b0 + 1) * 128 + 64 + c)) * N_ + node] = h1.f;
            unsigned long long wp = pk2(sWr[64 + c]);
            ffma2(rsp[0][0], wp, h0.u[0]);
            ffma2(rsp[0][1], wp, h0.u[1]);
            ffma2(rsp[1][0], wp, h1.u[0]);
            ffma2(rsp[1][1], wp, h1.u[1]);
        }

        // bias + PReLU + store conv outputs + conv readout partials
#pragma unroll
        for (int i = 0; i < 4; ++i) {
            int o = og * 4 + i;
            float bo = sBo[o];
            unsigned long long wrp = pk2(sWr[o]);
#pragma unroll
            for (int bb = 0; bb < 2; ++bb) {
                float2 a0 = upk2(ac[bb][i][0]);
                float2 a1 = upk2(ac[bb][i][1]);
                F4U vv;
                float x0 = a0.x + bo; x0 = (x0 >= 0.f) ? x0 : pw * x0;
                float x1 = a0.y + bo; x1 = (x1 >= 0.f) ? x1 : pw * x1;
                float x2 = a1.x + bo; x2 = (x2 >= 0.f) ? x2 : pw * x2;
                float x3 = a1.y + bo; x3 = (x3 >= 0.f) ? x3 : pw * x3;
                vv.f.x = x0; vv.f.y = x1; vv.f.z = x2; vv.f.w = x3;
                *(float4*)&out[((size_t)((b0 + bb) * 128 + o)) * N_ + node] = vv.f;
                ffma2(rsp[bb][0], wrp, vv.u[0]);
                ffma2(rsp[bb][1], wrp, vv.u[1]);
            }
        }

        // reduce readout partials across the 16 og-groups (in-warp butterfly)
        float rs[2][4];
#pragma unroll
        for (int bb = 0; bb < 2; ++bb) {
            float2 r0 = upk2(rsp[bb][0]);
            float2 r1 = upk2(rsp[bb][1]);
            rs[bb][0] = r0.x; rs[bb][1] = r0.y; rs[bb][2] = r1.x; rs[bb][3] = r1.y;
        }
#pragma unroll
        for (int mask = 1; mask < 16; mask <<= 1)
#pragma unroll
            for (int bb = 0; bb < 2; ++bb)
#pragma unroll
                for (int k = 0; k < 4; ++k)
                    rs[bb][k] += __shfl_xor_sync(0xFFFFFFFFu, rs[bb][k], mask);
        if (og == 0) {
#pragma unroll
            for (int bb = 0; bb < 2; ++bb) {
                float4 o4;
                o4.x = rs[bb][0] + brd; o4.y = rs[bb][1] + brd;
                o4.z = rs[bb][2] + brd; o4.w = rs[bb][3] + brd;
                *(float4*)&rd[(size_t)(b0 + bb) * N_ + node] = o4;
            }
        }
    }
}

extern "C" void kernel_launch(void* const* d_in, const int* in_sizes, int n_in,
                              void* d_out, int out_size) {
    const float* x       = (const float*)d_in[0];
    const float* m       = (const float*)d_in[1];
    const float* u       = (const float*)d_in[2];
    const float* h       = (const float*)d_in[3];
    const float* adj     = (const float*)d_in[4];
    const float* W_in    = (const float*)d_in[5];
    const float* b_in    = (const float*)d_in[6];
    const float* W_gc    = (const float*)d_in[7];
    const float* b_gc    = (const float*)d_in[8];
    const float* W_out   = (const float*)d_in[9];
    const float* b_out   = (const float*)d_in[10];
    const float* W_read  = (const float*)d_in[11];
    const float* b_read  = (const float*)d_in[12];
    const float* prelu_w = (const float*)d_in[13];

    float* read_out = (float*)d_out;
    float* out_big  = (float*)d_out + READ_ELEMS;

    static bool attr_set = false;
    if (!attr_set) {
        cudaFuncSetAttribute(k2_fused, cudaFuncAttributeMaxDynamicSharedMemorySize,
                             K2F_SMEM_BYTES);
        attr_set = true;
    }

    k0_combine<<<68, 128>>>(W_gc, W_in, b_in);
    k_cf<<<5, 256>>>();
    k_adjf<<<1024, 256>>>(adj);
    k1_yin<<<dim3(N_ / 128, B_), 256>>>(x, m, u, h);
    k2_fused<<<dim3(N_ / 128, (B_ * DMX) / 128), 256, K2F_SMEM_BYTES>>>(
        h, b_gc, W_out, b_out, prelu_w, W_read, b_read, out_big, read_out);
}

// round 14
// speedup vs baseline: 5.6413x; 1.1132x over previous
#include <cuda_runtime.h>
#include <cstdint>

// Problem constants
#define B_   128
#define N_   1024
#define DMX  64
#define DIN  68
#define READ_ELEMS (B_ * N_)

// Scratch (device globals; no allocations allowed)
__device__ float    g_C[2 * DMX * DIN];            // combined W_gc_s @ W_in (fp32)
__device__ float    g_cb[2 * DMX];                 // combined bias
__device__ uint32_t g_Cf[5 * 8 * 128];             // C as bf16 A-fragments (K padded to 80)
__device__ uint32_t g_Af[2 * 64 * 64 * 128];       // adj A-fragments (bf16)  4 MB
__device__ uint32_t g_Yf[2u * 1024 * 64 * 64];     // Y   B-fragments (bf16) 33.5 MB

// ================= f32x2 packed-FMA helpers =================
__device__ __forceinline__ unsigned long long pk2(float v) {
    unsigned long long r;
    asm("mov.b64 %0, {%1, %1};" : "=l"(r) : "f"(v));
    return r;
}
__device__ __forceinline__ void ffma2(unsigned long long& d,
                                      unsigned long long a,
                                      unsigned long long b) {
    asm("fma.rn.f32x2 %0, %1, %2, %0;" : "+l"(d) : "l"(a), "l"(b));
}
__device__ __forceinline__ float2 upk2(unsigned long long v) {
    float2 r;
    asm("mov.b64 {%0, %1}, %2;" : "=f"(r.x), "=f"(r.y) : "l"(v));
    return r;
}
union F4U { float4 f; unsigned long long u[2]; };

// ================= bf16 helpers =================
__device__ __forceinline__ uint32_t pack_bf16x2(float lo, float hi) {
    uint32_t r;
    asm("cvt.rn.bf16x2.f32 %0, %1, %2;" : "=r"(r) : "f"(hi), "f"(lo));
    return r;
}
__device__ __forceinline__ void mma_bf16(float* c, const uint32_t* a, const uint32_t* b) {
    asm volatile(
        "mma.sync.aligned.m16n8k16.row.col.f32.bf16.bf16.f32 "
        "{%0,%1,%2,%3}, {%4,%5,%6,%7}, {%8,%9}, {%0,%1,%2,%3};"
        : "+f"(c[0]), "+f"(c[1]), "+f"(c[2]), "+f"(c[3])
        : "r"(a[0]), "r"(a[1]), "r"(a[2]), "r"(a[3]),
          "r"(b[0]), "r"(b[1]));
}

// ================= K0: fold W_gc into W_in =================
__global__ void k0_combine(const float* __restrict__ W_gc,
                           const float* __restrict__ W_in,
                           const float* __restrict__ b_in) {
    int d = blockIdx.x;          // 0..67
    int t = threadIdx.x;         // 0..127 -> (s,o)
    int s = t >> 6, o = t & 63;
    const float* wg = W_gc + o * 128 + s * 64;
    float acc = 0.f;
#pragma unroll 8
    for (int c = 0; c < 64; ++c) acc += wg[c] * W_in[c * DIN + d];
    g_C[t * DIN + d] = acc;
    if (d == 0) {
        float ab = 0.f;
        for (int c = 0; c < 64; ++c) ab += wg[c] * b_in[c];
        g_cb[t] = ab;
    }
}

// ================= k_cf: pack C into bf16 A-fragments (K padded 68->80) =================
__device__ __forceinline__ float c_rd(int r, int d) {
    return (d < DIN) ? g_C[r * DIN + d] : 0.f;
}
__global__ void k_cf() {
    int wg   = blockIdx.x * 8 + (threadIdx.x >> 5);   // 0..39
    int lane = threadIdx.x & 31;
    int kc = wg >> 3, mf = wg & 7;
    int g = lane >> 2, p = lane & 3;
    int d0 = kc * 16 + 2 * p;
    int r0 = mf * 16 + g, r1 = r0 + 8;
    uint4 o;
    o.x = pack_bf16x2(c_rd(r0, d0),     c_rd(r0, d0 + 1));
    o.y = pack_bf16x2(c_rd(r1, d0),     c_rd(r1, d0 + 1));
    o.z = pack_bf16x2(c_rd(r0, d0 + 8), c_rd(r0, d0 + 9));
    o.w = pack_bf16x2(c_rd(r1, d0 + 8), c_rd(r1, d0 + 9));
    *(uint4*)&g_Cf[(kc * 8 + mf) * 128 + lane * 4] = o;
}

// ================= K1C: combined (k1_yin blocks 0..1023) + (k_adjf blocks 1024..2047) =========
__global__ void __launch_bounds__(256) k1_comb(const float* __restrict__ x,
                                               const float* __restrict__ m,
                                               const float* __restrict__ u,
                                               const float* __restrict__ h,
                                               const float* __restrict__ adj) {
    __shared__ uint32_t sP[128 * 44];
    const int bid = blockIdx.x;
    const int t = threadIdx.x;
    const int lane = t & 31;

    if (bid >= 1024) {
        // ---- adj repack into m16k16 A-fragments ----
        int wg = (bid - 1024) * 8 + (t >> 5);   // 0..8191
        int s  = wg >> 12;
        int mf = (wg >> 6) & 63;
        int kc = wg & 63;
        int g = lane >> 2, p = lane & 3;
        const float* rp = adj + ((size_t)(s * N_ + mf * 16 + g)) * N_ + kc * 16 + 2 * p;
        float2 v00 = *(const float2*)rp;
        float2 v10 = *(const float2*)(rp + 8 * N_);
        float2 v01 = *(const float2*)(rp + 8);
        float2 v11 = *(const float2*)(rp + 8 * N_ + 8);
        uint4 o;
        o.x = pack_bf16x2(v00.x, v00.y);
        o.y = pack_bf16x2(v10.x, v10.y);
        o.z = pack_bf16x2(v01.x, v01.y);
        o.w = pack_bf16x2(v11.x, v11.y);
        *(uint4*)&g_Af[(size_t)wg * 128 + lane * 4] = o;
        return;
    }

    // ---- K1: Y = bf16 MMA (C @ cat(x,m,u,h)) + cb -> B-frags direct ----
    const int b  = bid >> 3;
    const int v0 = (bid & 7) * 128;
    const int w  = t >> 5;
    const int g  = lane >> 2, p = lane & 3;

    for (int e = t; e < 40 * 128; e += 256) {
        int dp = e >> 7, nd = e & 127;
        int v = v0 + nd;
        float lo, hi;
        if (dp == 0)       { lo = x[b * N_ + v];             hi = m[b * N_ + v]; }
        else if (dp == 1)  { lo = u[(2 * b) * N_ + v];       hi = u[(2 * b + 1) * N_ + v]; }
        else if (dp < 34)  {
            int c = 2 * dp - 4;
            lo = h[((size_t)b * 64 + c) * N_ + v];
            hi = h[((size_t)b * 64 + c + 1) * N_ + v];
        } else             { lo = 0.f; hi = 0.f; }
        sP[nd * 44 + dp] = pack_bf16x2(lo, hi);
    }
    __syncthreads();

    uint4 Af[5];
#pragma unroll
    for (int kc = 0; kc < 5; ++kc)
        Af[kc] = *(const uint4*)&g_Cf[(kc * 8 + w) * 128 + lane * 4];

    float acc[16][4];
#pragma unroll
    for (int i = 0; i < 16; ++i)
#pragma unroll
        for (int c = 0; c < 4; ++c) acc[i][c] = 0.f;

#pragma unroll
    for (int kc = 0; kc < 5; ++kc) {
#pragma unroll
        for (int nf8 = 0; nf8 < 16; ++nf8) {
            uint32_t bf[2];
            bf[0] = sP[(nf8 * 8 + g) * 44 + 8 * kc + p];
            bf[1] = sP[(nf8 * 8 + g) * 44 + 8 * kc + p + 4];
            mma_bf16(acc[nf8], (const uint32_t*)&Af[kc], bf);
        }
    }

    const int s = w >> 2;
    const float cb0 = g_cb[w * 16 + g];
    const float cb1 = g_cb[w * 16 + 8 + g];
    const int nfl0 = (w & 3) * 2;
    const size_t base0 = ((size_t)(s * 1024 + b * 8 + nfl0)) * 4096;
    const size_t base1 = base0 + 4096;
    const int off = (g * 4 + p) * 2;
    const int kc0 = v0 >> 4;
#pragma unroll
    for (int e = 0; e < 8; ++e) {
        uint2 lo_v, hi_v;
        lo_v.x = pack_bf16x2(acc[2 * e][0] + cb0, acc[2 * e][1] + cb0);
        lo_v.y = pack_bf16x2(acc[2 * e + 1][0] + cb0, acc[2 * e + 1][1] + cb0);
        hi_v.x = pack_bf16x2(acc[2 * e][2] + cb1, acc[2 * e][3] + cb1);
        hi_v.y = pack_bf16x2(acc[2 * e + 1][2] + cb1, acc[2 * e + 1][3] + cb1);
        *(uint2*)&g_Yf[base0 + (size_t)(kc0 + e) * 64 + off] = lo_v;
        *(uint2*)&g_Yf[base1 + (size_t)(kc0 + e) * 64 + off] = hi_v;
    }
}

// ================= K2F: fragment-direct bf16 MMA + FUSED out-conv/PReLU/h-copy/readout ========
// Dynamic smem layout (floats):
//   sTF  [128 ch][132]      0     .. 16896   (67,584 B)
//   sWoF [128 c ][68 o]     16896 .. 25600   (34,816 B)
//   sWr  [128]              25600 .. 25728
//   sBo  [64]               25728 .. 25792
#define K2F_SMEM_BYTES (25792 * 4)

__global__ void __launch_bounds__(256, 2) k2_fused(
    const float* __restrict__ h, const float* __restrict__ b_gc,
    const float* __restrict__ W_out, const float* __restrict__ b_out,
    const float* __restrict__ prelu_w, const float* __restrict__ W_read,
    const float* __restrict__ b_read,
    float* __restrict__ out, float* __restrict__ rd) {
    extern __shared__ __align__(16) float SMF[];
    float* sTF  = SMF;
    float* sWoF = SMF + 16896;
    float* sWr  = SMF + 25600;
    float* sBo  = SMF + 25728;

    const int t = threadIdx.x, lane = t & 31, wid = t >> 5;
    const int wm = wid >> 2, wn = wid & 3;
    const int w0 = blockIdx.x * 128;
    const int r0 = blockIdx.y * 128;
    const int b0 = blockIdx.y * 2;

    // One-time weight staging (coalesced gmem reads)
    for (int e = t; e < 8192; e += 256) {
        int c = e & 127, o = e >> 7;
        sWoF[c * 68 + o] = W_out[o * 128 + c];
    }
    if (t < 128) sWr[t] = W_read[t];
    if (t < 64)  sBo[t] = b_out[t];

    // ---- MMA mainloop ----
    const uint32_t* aBase = g_Af + (size_t)((w0 >> 4) + wm * 4) * (64 * 128) + lane * 4;
    const uint32_t* bBase = g_Yf + (size_t)((r0 >> 3) + wn * 4) * (64 * 64) + lane * 2;

    float acc[4][4][4];
#pragma unroll
    for (int i = 0; i < 4; ++i)
#pragma unroll
        for (int j = 0; j < 4; ++j)
#pragma unroll
            for (int c = 0; c < 4; ++c) acc[i][j][c] = 0.f;

    uint4 Ab[2][4];
    uint2 Bb[2][4];
#pragma unroll
    for (int i = 0; i < 4; ++i) Ab[0][i] = *(const uint4*)(aBase + i * 8192);
#pragma unroll
    for (int j = 0; j < 4; ++j) Bb[0][j] = *(const uint2*)(bBase + j * 4096);

    for (int kc = 0; kc < 128; ++kc) {
        const int cur = kc & 1;
        if (kc < 127) {
            const int kn = kc + 1;
            const uint32_t* ap = aBase + (kn >> 6) * (64 * 64 * 128) + (kn & 63) * 128;
            const uint32_t* bp = bBase + (kn >> 6) * (1024 * 64 * 64) + (kn & 63) * 64;
#pragma unroll
            for (int i = 0; i < 4; ++i) Ab[cur ^ 1][i] = *(const uint4*)(ap + i * 8192);
#pragma unroll
            for (int j = 0; j < 4; ++j) Bb[cur ^ 1][j] = *(const uint2*)(bp + j * 4096);
        }
#pragma unroll
        for (int i = 0; i < 4; ++i)
#pragma unroll
            for (int j = 0; j < 4; ++j)
                mma_bf16(acc[i][j], (const uint32_t*)&Ab[cur][i],
                         (const uint32_t*)&Bb[cur][j]);
    }

    // ---- Transpose accumulators (+ b_gc bias) into full sTF tile ----
    const int g = lane >> 2, tq = lane & 3;
#pragma unroll
    for (int i = 0; i < 4; ++i) {
        int wl = wm * 64 + i * 16 + g;
#pragma unroll
        for (int j = 0; j < 4; ++j) {
            int rl = wn * 32 + j * 8 + 2 * tq;
            float bias0 = b_gc[rl & 63];
            float bias1 = b_gc[(rl + 1) & 63];
            sTF[rl * 132 + wl]            = acc[i][j][0] + bias0;
            sTF[(rl + 1) * 132 + wl]      = acc[i][j][1] + bias1;
            sTF[rl * 132 + wl + 8]        = acc[i][j][2] + bias0;
            sTF[(rl + 1) * 132 + wl + 8]  = acc[i][j][3] + bias1;
        }
    }
    __syncthreads();

    // ---- Fused epilogue (og8 x nq32): out-conv + PReLU + h-copy + readout ----
    const int og = t & 7;             // o-group: o = og*8..+7; h-channels og*8..+7
    const int nq = t >> 3;            // node quad 0..31 (covers all 128 nodes)
    const int node = w0 + nq * 4;
    const float pw = prelu_w[0];
    const float brd = b_read[0];
    const float* col = sTF + nq * 4;
    const float* hb0 = h + (size_t)(b0 * 64) * N_ + node;
    const float* hb1 = hb0 + (size_t)64 * N_;

    unsigned long long ac[2][8][2];
#pragma unroll
    for (int bb = 0; bb < 2; ++bb)
#pragma unroll
        for (int i = 0; i < 8; ++i) { ac[bb][i][0] = 0ull; ac[bb][i][1] = 0ull; }
    unsigned long long rsp[2][2] = {0ull, 0ull, 0ull, 0ull};

    // gc channels (from smem tile)
#pragma unroll 4
    for (int c = 0; c < 64; ++c) {
        F4U v0; v0.f = *(const float4*)(col + c * 132);
        F4U v1; v1.f = *(const float4*)(col + (64 + c) * 132);
        float4 wq0 = *(const float4*)&sWoF[c * 68 + og * 8];
        float4 wq1 = *(const float4*)&sWoF[c * 68 + og * 8 + 4];
        const float* wf0 = (const float*)&wq0;
        const float* wf1 = (const float*)&wq1;
#pragma unroll
        for (int i = 0; i < 4; ++i) {
            unsigned long long wp = pk2(wf0[i]);
            ffma2(ac[0][i][0], wp, v0.u[0]);
            ffma2(ac[0][i][1], wp, v0.u[1]);
            ffma2(ac[1][i][0], wp, v1.u[0]);
            ffma2(ac[1][i][1], wp, v1.u[1]);
        }
#pragma unroll
        for (int i = 0; i < 4; ++i) {
            unsigned long long wp = pk2(wf1[i]);
            ffma2(ac[0][4 + i][0], wp, v0.u[0]);
            ffma2(ac[0][4 + i][1], wp, v0.u[1]);
            ffma2(ac[1][4 + i][0], wp, v1.u[0]);
            ffma2(ac[1][4 + i][1], wp, v1.u[1]);
        }
    }
    // h channels (from gmem) + h-copy + h-readout for own channel range
#pragma unroll 4
    for (int c = 0; c < 64; ++c) {
        F4U h0; h0.f = *(const float4*)(hb0 + (size_t)c * N_);
        F4U h1; h1.f = *(const float4*)(hb1 + (size_t)c * N_);
        float4 wq0 = *(const float4*)&sWoF[(64 + c) * 68 + og * 8];
        float4 wq1 = *(const float4*)&sWoF[(64 + c) * 68 + og * 8 + 4];
        const float* wf0 = (const float*)&wq0;
        const float* wf1 = (const float*)&wq1;
#pragma unroll
        for (int i = 0; i < 4; ++i) {
            unsigned long long wp = pk2(wf0[i]);
            ffma2(ac[0][i][0], wp, h0.u[0]);
            ffma2(ac[0][i][1], wp, h0.u[1]);
            ffma2(ac[1][i][0], wp, h1.u[0]);
            ffma2(ac[1][i][1], wp, h1.u[1]);
        }
#pragma unroll
        for (int i = 0; i < 4; ++i) {
            unsigned long long wp = pk2(wf1[i]);
            ffma2(ac[0][4 + i][0], wp, h0.u[0]);
            ffma2(ac[0][4 + i][1], wp, h0.u[1]);
            ffma2(ac[1][4 + i][0], wp, h1.u[0]);
            ffma2(ac[1][4 + i][1], wp, h1.u[1]);
        }
        if ((c >> 3) == og) {
            *(float4*)&out[((size_t)(b0 * 128 + 64 + c)) * N_ + node] = h0.f;
            *(float4*)&out[((size_t)((b0 + 1) * 128 + 64 + c)) * N_ + node] = h1.f;
            unsigned long long wp = pk2(sWr[64 + c]);
            ffma2(rsp[0][0], wp, h0.u[0]);
            ffma2(rsp[0][1], wp, h0.u[1]);
            ffma2(rsp[1][0], wp, h1.u[0]);
            ffma2(rsp[1][1], wp, h1.u[1]);
        }
    }

    // bias + PReLU + store conv outputs + conv readout partials
#pragma unroll
    for (int i = 0; i < 8; ++i) {
        int o = og * 8 + i;
        float bo = sBo[o];
        unsigned long long wrp = pk2(sWr[o]);
#pragma unroll
        for (int bb = 0; bb < 2; ++bb) {
            float2 a0 = upk2(ac[bb][i][0]);
            float2 a1 = upk2(ac[bb][i][1]);
            F4U vv;
            float x0 = a0.x + bo; x0 = (x0 >= 0.f) ? x0 : pw * x0;
            float x1 = a0.y + bo; x1 = (x1 >= 0.f) ? x1 : pw * x1;
            float x2 = a1.x + bo; x2 = (x2 >= 0.f) ? x2 : pw * x2;
            float x3 = a1.y + bo; x3 = (x3 >= 0.f) ? x3 : pw * x3;
            vv.f.x = x0; vv.f.y = x1; vv.f.z = x2; vv.f.w = x3;
            *(float4*)&out[((size_t)((b0 + bb) * 128 + o)) * N_ + node] = vv.f;
            ffma2(rsp[bb][0], wrp, vv.u[0]);
            ffma2(rsp[bb][1], wrp, vv.u[1]);
        }
    }

    // reduce readout partials across the 8 og-groups (in-warp butterfly)
    float rs[2][4];
#pragma unroll
    for (int bb = 0; bb < 2; ++bb) {
        float2 r0 = upk2(rsp[bb][0]);
        float2 r1 = upk2(rsp[bb][1]);
        rs[bb][0] = r0.x; rs[bb][1] = r0.y; rs[bb][2] = r1.x; rs[bb][3] = r1.y;
    }
#pragma unroll
    for (int mask = 1; mask < 8; mask <<= 1)
#pragma unroll
        for (int bb = 0; bb < 2; ++bb)
#pragma unroll
            for (int k = 0; k < 4; ++k)
                rs[bb][k] += __shfl_xor_sync(0xFFFFFFFFu, rs[bb][k], mask);
    if (og == 0) {
#pragma unroll
        for (int bb = 0; bb < 2; ++bb) {
            float4 o4;
            o4.x = rs[bb][0] + brd; o4.y = rs[bb][1] + brd;
            o4.z = rs[bb][2] + brd; o4.w = rs[bb][3] + brd;
            *(float4*)&rd[(size_t)(b0 + bb) * N_ + node] = o4;
        }
    }
}

extern "C" void kernel_launch(void* const* d_in, const int* in_sizes, int n_in,
                              void* d_out, int out_size) {
    const float* x       = (const float*)d_in[0];
    const float* m       = (const float*)d_in[1];
    const float* u       = (const float*)d_in[2];
    const float* h       = (const float*)d_in[3];
    const float* adj     = (const float*)d_in[4];
    const float* W_in    = (const float*)d_in[5];
    const float* b_in    = (const float*)d_in[6];
    const float* W_gc    = (const float*)d_in[7];
    const float* b_gc    = (const float*)d_in[8];
    const float* W_out   = (const float*)d_in[9];
    const float* b_out   = (const float*)d_in[10];
    const float* W_read  = (const float*)d_in[11];
    const float* b_read  = (const float*)d_in[12];
    const float* prelu_w = (const float*)d_in[13];

    float* read_out = (float*)d_out;
    float* out_big  = (float*)d_out + READ_ELEMS;

    static bool attr_set = false;
    if (!attr_set) {
        cudaFuncSetAttribute(k2_fused, cudaFuncAttributeMaxDynamicSharedMemorySize,
                             K2F_SMEM_BYTES);
        attr_set = true;
    }

    k0_combine<<<68, 128>>>(W_gc, W_in, b_in);
    k_cf<<<5, 256>>>();
    k1_comb<<<2048, 256>>>(x, m, u, h, adj);
    k2_fused<<<dim3(N_ / 128, (B_ * DMX) / 128), 256, K2F_SMEM_BYTES>>>(
        h, b_gc, W_out, b_out, prelu_w, W_read, b_read, out_big, read_out);
}